// round 6
// baseline (speedup 1.0000x reference)
#include <cuda_runtime.h>
#include <cuda_bf16.h>
#include <math.h>
#include <stdint.h>

// ---------------- problem constants ----------------
#define NEMBD   2048
#define NH      16
#define DH      128
#define BATCH   2
#define SEQ     2048
#define MROWS   (BATCH*SEQ)     // 4096
#define QKV_N   (3*NEMBD)       // 6144
#define BHN     (BATCH*NH)      // 32

// ---------------- scratch (device globals, no runtime allocs) ----------------
__device__ float g_qkv[(size_t)MROWS * QKV_N];
__device__ float g_q[(size_t)BHN*SEQ*DH];
__device__ __nv_bfloat16 g_khi[(size_t)BHN*SEQ*DH];
__device__ __nv_bfloat16 g_klo[(size_t)BHN*SEQ*DH];
__device__ __nv_bfloat16 g_vhi[(size_t)BHN*SEQ*DH];
__device__ __nv_bfloat16 g_vlo[(size_t)BHN*SEQ*DH];
__device__ __nv_bfloat16 g_xhi[(size_t)MROWS*NEMBD];
__device__ __nv_bfloat16 g_xlo[(size_t)MROWS*NEMBD];
__device__ __nv_bfloat16 g_wqh[(size_t)QKV_N*NEMBD];
__device__ __nv_bfloat16 g_wql[(size_t)QKV_N*NEMBD];
__device__ __nv_bfloat16 g_wph[(size_t)NEMBD*NEMBD];
__device__ __nv_bfloat16 g_wpl[(size_t)NEMBD*NEMBD];
__device__ __nv_bfloat16 g_yhi[(size_t)MROWS*NEMBD];
__device__ __nv_bfloat16 g_ylo[(size_t)MROWS*NEMBD];
__device__ float g_cos[SEQ*64];
__device__ float g_sin[SEQ*64];

// ================= common asm helpers =================
#define MMA16816(d, a0, a1, a2, a3, b0, b1)                                \
    asm volatile(                                                          \
        "mma.sync.aligned.m16n8k16.row.col.f32.bf16.bf16.f32 "             \
        "{%0,%1,%2,%3}, {%4,%5,%6,%7}, {%8,%9}, {%0,%1,%2,%3};"            \
        : "+f"((d)[0]), "+f"((d)[1]), "+f"((d)[2]), "+f"((d)[3])           \
        : "r"(a0), "r"(a1), "r"(a2), "r"(a3), "r"(b0), "r"(b1))

#define LDSM_X4(r0, r1, r2, r3, addr)                                       \
    asm volatile("ldmatrix.sync.aligned.m8n8.x4.shared.b16 "                \
                 "{%0,%1,%2,%3}, [%4];"                                     \
                 : "=r"(r0), "=r"(r1), "=r"(r2), "=r"(r3) : "r"(addr))

#define LDSM_X4T(r0, r1, r2, r3, addr)                                      \
    asm volatile("ldmatrix.sync.aligned.m8n8.x4.trans.shared.b16 "          \
                 "{%0,%1,%2,%3}, [%4];"                                     \
                 : "=r"(r0), "=r"(r1), "=r"(r2), "=r"(r3) : "r"(addr))

#define CP_ASYNC16(dst, src)                                                \
    asm volatile("cp.async.cg.shared.global [%0], [%1], 16;"                \
                 :: "r"(dst), "l"(src))
#define CP_COMMIT() asm volatile("cp.async.commit_group;" ::: "memory")
#define CP_WAIT1()  asm volatile("cp.async.wait_group 1;" ::: "memory")
#define CP_WAIT0()  asm volatile("cp.async.wait_group 0;" ::: "memory")

__device__ __forceinline__ uint32_t smem_u32(const void* p) {
    uint32_t a;
    asm("{ .reg .u64 t; cvta.to.shared.u64 t, %1; cvt.u32.u64 %0, t; }"
        : "=r"(a) : "l"(p));
    return a;
}

__device__ __forceinline__ void bf16_split2(float x, float y,
                                            uint32_t& hi, uint32_t& lo) {
    __nv_bfloat162 h = __floats2bfloat162_rn(x, y);
    float rx = x - __bfloat162float(__low2bfloat16(h));
    float ry = y - __bfloat162float(__high2bfloat16(h));
    __nv_bfloat162 l = __floats2bfloat162_rn(rx, ry);
    hi = *(uint32_t*)&h;
    lo = *(uint32_t*)&l;
}

// ================= RoPE tables (fp64 angles) =================
__global__ void rope_table_kernel(float* gcos, float* gsin) {
    int idx = blockIdx.x * blockDim.x + threadIdx.x;
    if (idx >= SEQ * 64) return;
    int t = idx >> 6;
    int i = idx & 63;
    double freq = exp(-((double)(2 * i) / 128.0) * log(10000.0));
    double ang = (double)t * freq;
    gcos[idx] = (float)cos(ang);
    gsin[idx] = (float)sin(ang);
}

// ================= fp32 -> bf16 hi/lo split (one-shot pass) ==================
__global__ void split_kernel(const float* __restrict__ src,
                             __nv_bfloat16* __restrict__ hi,
                             __nv_bfloat16* __restrict__ lo, long long n4) {
    long long i = (long long)blockIdx.x * blockDim.x + threadIdx.x;
    if (i >= n4) return;
    float4 v = *(const float4*)(src + i * 4);
    uint32_t h01, l01, h23, l23;
    bf16_split2(v.x, v.y, h01, l01);
    bf16_split2(v.z, v.w, h23, l23);
    *(uint2*)(hi + i * 4) = make_uint2(h01, h23);
    *(uint2*)(lo + i * 4) = make_uint2(l01, l23);
}

// ========== bf16-split HMMA GEMM (pre-split, cp.async DB, ldmatrix) =========
// C[M,N] = (AH+AL)[M,K] * (BH+BL)[N,K]^T  (split-3 accumulate)
#define GARR 10240                 // bytes per array per stage (128 rows * 80B)
#define GSTG (4*GARR)              // 40960 B per stage
#define GEMM_SMEM (2*GSTG)         // 81920 B

__global__ __launch_bounds__(256, 2)
void gemm_bf16_kernel(const __nv_bfloat16* __restrict__ AH,
                      const __nv_bfloat16* __restrict__ AL,
                      const __nv_bfloat16* __restrict__ BH,
                      const __nv_bfloat16* __restrict__ BL,
                      float* __restrict__ C, int M, int N, int K) {
    extern __shared__ char gsm[];
    const uint32_t sb = smem_u32(gsm);

    const int tid  = threadIdx.x;
    const int warp = tid >> 5, lane = tid & 31;
    const int g = lane >> 2, t = lane & 3;
    const int wm = warp & 3, wn = warp >> 2;     // 4x2 warps; warp tile 32x64
    const int m0 = blockIdx.y * 128;
    const int n0 = blockIdx.x * 128;
    const int NT = K / 32;

    float acc[2][8][4];
#pragma unroll
    for (int mf = 0; mf < 2; mf++)
#pragma unroll
        for (int nf = 0; nf < 8; nf++)
#pragma unroll
            for (int r = 0; r < 4; r++) acc[mf][nf][r] = 0.0f;

    auto prefetch = [&](int s, int kt) {
#pragma unroll
        for (int it = 0; it < 8; it++) {
            int i = tid + it * 256;
            int arr = i >> 9;            // 0..3 : AH,AL,BH,BL
            int row = (i >> 2) & 127;
            int ch  = i & 3;
            const __nv_bfloat16* src =
                (arr == 0) ? AH + (size_t)(m0 + row) * K :
                (arr == 1) ? AL + (size_t)(m0 + row) * K :
                (arr == 2) ? BH + (size_t)(n0 + row) * K :
                             BL + (size_t)(n0 + row) * K;
            src += kt * 32 + ch * 8;
            uint32_t dst = sb + (uint32_t)(s * GSTG + arr * GARR + row * 80 + ch * 16);
            CP_ASYNC16(dst, src);
        }
    };

    prefetch(0, 0);
    CP_COMMIT();

    // ldmatrix per-lane offsets (within one array, at kk=0)
    const uint32_t lmA = (uint32_t)((wm * 32 + (lane & 15)) * 80
                                    + ((lane >> 4) << 3) * 2);
    const uint32_t lmB = (uint32_t)((wn * 64 + (lane & 15)) * 80
                                    + ((lane >> 4) << 3) * 2);

    for (int kt = 0; kt < NT; kt++) {
        if (kt + 1 < NT) {
            prefetch((kt + 1) & 1, kt + 1);
            CP_COMMIT();
            CP_WAIT1();
        } else {
            CP_WAIT0();
        }
        __syncthreads();

        const uint32_t stg = sb + (uint32_t)((kt & 1) * GSTG);

#pragma unroll
        for (int kk = 0; kk < 32; kk += 16) {
            const uint32_t kb = (uint32_t)(kk * 2);
            uint32_t ah[2][4], al[2][4];
#pragma unroll
            for (int mf = 0; mf < 2; mf++) {
                uint32_t aaddr = stg + lmA + (uint32_t)(mf * 16 * 80) + kb;
                LDSM_X4(ah[mf][0], ah[mf][1], ah[mf][2], ah[mf][3], aaddr);
                LDSM_X4(al[mf][0], al[mf][1], al[mf][2], al[mf][3], aaddr + GARR);
            }
#pragma unroll
            for (int pr = 0; pr < 4; pr++) {
                uint32_t baddr = stg + 2u * GARR + lmB + (uint32_t)(pr * 16 * 80) + kb;
                uint32_t bh0, bh1, bh2, bh3, bl0, bl1, bl2, bl3;
                LDSM_X4(bh0, bh1, bh2, bh3, baddr);
                LDSM_X4(bl0, bl1, bl2, bl3, baddr + GARR);
                // ldsm.x4 on 16 N-rows x 16 K: (r0,r2) = frag for nf=2*pr,
                //                              (r1,r3) = frag for nf=2*pr+1
#pragma unroll
                for (int mf = 0; mf < 2; mf++) {
                    MMA16816(acc[mf][2*pr],   ah[mf][0], ah[mf][1], ah[mf][2], ah[mf][3], bh0, bh2);
                    MMA16816(acc[mf][2*pr],   ah[mf][0], ah[mf][1], ah[mf][2], ah[mf][3], bl0, bl2);
                    MMA16816(acc[mf][2*pr],   al[mf][0], al[mf][1], al[mf][2], al[mf][3], bh0, bh2);
                    MMA16816(acc[mf][2*pr+1], ah[mf][0], ah[mf][1], ah[mf][2], ah[mf][3], bh1, bh3);
                    MMA16816(acc[mf][2*pr+1], ah[mf][0], ah[mf][1], ah[mf][2], ah[mf][3], bl1, bl3);
                    MMA16816(acc[mf][2*pr+1], al[mf][0], al[mf][1], al[mf][2], al[mf][3], bh1, bh3);
                }
            }
        }
        __syncthreads();
    }

#pragma unroll
    for (int mf = 0; mf < 2; mf++) {
        int r0 = m0 + wm * 32 + mf * 16 + g;
#pragma unroll
        for (int nf = 0; nf < 8; nf++) {
            int col = n0 + wn * 64 + nf * 8 + 2 * t;
            float* p0 = C + (size_t)r0 * N + col;
            float* p1 = C + (size_t)(r0 + 8) * N + col;
            *(float2*)p0 = make_float2(acc[mf][nf][0], acc[mf][nf][1]);
            *(float2*)p1 = make_float2(acc[mf][nf][2], acc[mf][nf][3]);
        }
    }
}

// ======== RoPE apply + transpose; emit Q fp32 and K/V bf16 hi/lo =============
__global__ void rope_apply_kernel(const float* __restrict__ qkv,
                                  const float* __restrict__ gcos,
                                  const float* __restrict__ gsin,
                                  float* __restrict__ q,
                                  __nv_bfloat16* __restrict__ khi,
                                  __nv_bfloat16* __restrict__ klo,
                                  __nv_bfloat16* __restrict__ vhi,
                                  __nv_bfloat16* __restrict__ vlo) {
    long long idx = (long long)blockIdx.x * blockDim.x + threadIdx.x;
    const long long total = (long long)BHN * SEQ * DH;
    if (idx >= total) return;
    int d  = (int)(idx & 127);
    int t  = (int)((idx >> 7) & (SEQ - 1));
    int bh = (int)(idx >> 18);
    int b  = bh >> 4;
    int h  = bh & 15;

    size_t base = ((size_t)(b * SEQ + t)) * QKV_N + (size_t)h * DH;
    float qv = qkv[base + d];
    float kv = qkv[base + NEMBD + d];
    float vv = qkv[base + 2 * NEMBD + d];

    int ci = d & 63;
    float c = gcos[t * 64 + ci];
    float s = gsin[t * 64 + ci];
    float qr, kr;
    if (d < 64) {
        qr = -qkv[base + d + 64];
        kr = -qkv[base + NEMBD + d + 64];
    } else {
        qr = qkv[base + d - 64];
        kr = qkv[base + NEMBD + d - 64];
    }

    size_t o = ((size_t)bh * SEQ + t) * DH + d;
    q[o] = qv * c + qr * s;

    float kval = kv * c + kr * s;
    __nv_bfloat16 kh = __float2bfloat16(kval);
    khi[o] = kh;
    klo[o] = __float2bfloat16(kval - __bfloat162float(kh));

    __nv_bfloat16 vh = __float2bfloat16(vv);
    vhi[o] = vh;
    vlo[o] = __float2bfloat16(vv - __bfloat162float(vh));
}

// ================= flash attention on HMMA (bf16 split-3) ====================
#define FBQ 128
#define FBK 64
#define FLD 136
#define STG_B (4 * 17408)
#define FA2_SMEM (2 * STG_B)

__global__ __launch_bounds__(256, 1)
void flash_mma_kernel(const float* __restrict__ Qg,
                      const __nv_bfloat16* __restrict__ KH,
                      const __nv_bfloat16* __restrict__ KL,
                      const __nv_bfloat16* __restrict__ VH,
                      const __nv_bfloat16* __restrict__ VL,
                      __nv_bfloat16* __restrict__ Yh,
                      __nv_bfloat16* __restrict__ Yl) {
    extern __shared__ char smc[];
    const uint32_t sbase = smem_u32(smc);

    const int tid  = threadIdx.x;
    const int w    = tid >> 5, lane = tid & 31;
    const int g    = lane >> 2, t = lane & 3;
    const int qi   = gridDim.x - 1 - blockIdx.x;
    const int bh   = blockIdx.y;
    const int qbase = qi * FBQ;
    const int rowmax_w = qbase + w * 16 + 15;

    const size_t bhoff = (size_t)bh * SEQ * DH;

    const float scale = 0.08838834764831845f;
    uint32_t qh[8][4], ql[8][4];
    {
        const float* q0 = Qg + bhoff + (size_t)(qbase + w * 16 + g) * DH;
        const float* q1 = q0 + 8 * DH;
#pragma unroll
        for (int kf = 0; kf < 8; kf++) {
            float2 v00 = *(const float2*)(q0 + 16 * kf + 2 * t);
            float2 v10 = *(const float2*)(q1 + 16 * kf + 2 * t);
            float2 v01 = *(const float2*)(q0 + 16 * kf + 2 * t + 8);
            float2 v11 = *(const float2*)(q1 + 16 * kf + 2 * t + 8);
            bf16_split2(v00.x * scale, v00.y * scale, qh[kf][0], ql[kf][0]);
            bf16_split2(v10.x * scale, v10.y * scale, qh[kf][1], ql[kf][1]);
            bf16_split2(v01.x * scale, v01.y * scale, qh[kf][2], ql[kf][2]);
            bf16_split2(v11.x * scale, v11.y * scale, qh[kf][3], ql[kf][3]);
        }
    }

    const uint32_t lmK = (uint32_t)(((lane & 7) * FLD + (lane >> 3) * 8) * 2);
    const uint32_t lmV = (uint32_t)((((lane & 7) + ((lane >> 3) & 1) * 8) * FLD
                                     + (lane >> 4) * 8) * 2);

    float m0r = -1e30f, m1r = -1e30f, l0r = 0.0f, l1r = 0.0f;
    float o[16][4];
#pragma unroll
    for (int nf = 0; nf < 16; nf++)
#pragma unroll
        for (int r = 0; r < 4; r++) o[nf][r] = 0.0f;

    const int nkt = 2 * qi + 2;

    auto prefetch = [&](int s, int kt) {
        const int kb = kt * FBK;
        const __nv_bfloat16* srcs[4] = {
            KH + bhoff + (size_t)kb * DH, KL + bhoff + (size_t)kb * DH,
            VH + bhoff + (size_t)kb * DH, VL + bhoff + (size_t)kb * DH };
        uint32_t dst0 = sbase + (uint32_t)s * STG_B;
#pragma unroll
        for (int it = 0; it < 16; it++) {
            int i = tid + it * 256;
            int arr = i >> 10, key = (i >> 4) & 63, ch = i & 15;
            const __nv_bfloat16* src = srcs[arr] + key * DH + ch * 8;
            uint32_t dst = dst0 + (uint32_t)(arr * 17408 + key * 272 + ch * 16);
            CP_ASYNC16(dst, src);
        }
    };

    prefetch(0, 0);
    CP_COMMIT();

    for (int kt = 0; kt < nkt; kt++) {
        if (kt + 1 < nkt) {
            prefetch((kt + 1) & 1, kt + 1);
            CP_COMMIT();
            CP_WAIT1();
        } else {
            CP_WAIT0();
        }
        __syncthreads();

        const int kbase = kt * FBK;
        const bool active = (kbase <= rowmax_w);
        if (active) {
            const uint32_t stg = sbase + (uint32_t)(kt & 1) * STG_B;

            float s[8][4];
#pragma unroll
            for (int nf = 0; nf < 8; nf++)
#pragma unroll
                for (int r = 0; r < 4; r++) s[nf][r] = 0.0f;

#pragma unroll
            for (int kf2 = 0; kf2 < 4; kf2++) {
#pragma unroll
                for (int nf = 0; nf < 8; nf++) {
                    uint32_t off = (uint32_t)((nf * 8 * FLD + kf2 * 32) * 2);
                    uint32_t bh0, bh1, bh2, bh3, bl0, bl1, bl2, bl3;
                    LDSM_X4(bh0, bh1, bh2, bh3, stg + lmK + off);
                    LDSM_X4(bl0, bl1, bl2, bl3, stg + 17408u + lmK + off);
                    MMA16816(s[nf], qh[2*kf2][0], qh[2*kf2][1], qh[2*kf2][2], qh[2*kf2][3], bh0, bh1);
                    MMA16816(s[nf], qh[2*kf2][0], qh[2*kf2][1], qh[2*kf2][2], qh[2*kf2][3], bl0, bl1);
                    MMA16816(s[nf], ql[2*kf2][0], ql[2*kf2][1], ql[2*kf2][2], ql[2*kf2][3], bh0, bh1);
                    MMA16816(s[nf], qh[2*kf2+1][0], qh[2*kf2+1][1], qh[2*kf2+1][2], qh[2*kf2+1][3], bh2, bh3);
                    MMA16816(s[nf], qh[2*kf2+1][0], qh[2*kf2+1][1], qh[2*kf2+1][2], qh[2*kf2+1][3], bl2, bl3);
                    MMA16816(s[nf], ql[2*kf2+1][0], ql[2*kf2+1][1], ql[2*kf2+1][2], ql[2*kf2+1][3], bh2, bh3);
                }
            }

            const int row0 = qbase + w * 16 + g;
            const int row1 = row0 + 8;
            if (kbase + FBK - 1 > qbase + w * 16) {
#pragma unroll
                for (int nf = 0; nf < 8; nf++) {
                    int c0 = kbase + 8 * nf + 2 * t;
                    if (c0 > row0)     s[nf][0] = -1e30f;
                    if (c0 + 1 > row0) s[nf][1] = -1e30f;
                    if (c0 > row1)     s[nf][2] = -1e30f;
                    if (c0 + 1 > row1) s[nf][3] = -1e30f;
                }
            }

            float mx0 = -1e30f, mx1 = -1e30f;
#pragma unroll
            for (int nf = 0; nf < 8; nf++) {
                mx0 = fmaxf(mx0, fmaxf(s[nf][0], s[nf][1]));
                mx1 = fmaxf(mx1, fmaxf(s[nf][2], s[nf][3]));
            }
            mx0 = fmaxf(mx0, __shfl_xor_sync(0xffffffffu, mx0, 1));
            mx0 = fmaxf(mx0, __shfl_xor_sync(0xffffffffu, mx0, 2));
            mx1 = fmaxf(mx1, __shfl_xor_sync(0xffffffffu, mx1, 1));
            mx1 = fmaxf(mx1, __shfl_xor_sync(0xffffffffu, mx1, 2));
            float mn0 = fmaxf(m0r, mx0), mn1 = fmaxf(m1r, mx1);
            float a0 = __expf(m0r - mn0), a1 = __expf(m1r - mn1);
            m0r = mn0; m1r = mn1;
            float rs0 = 0.0f, rs1 = 0.0f;
#pragma unroll
            for (int nf = 0; nf < 8; nf++) {
                s[nf][0] = __expf(s[nf][0] - mn0);
                s[nf][1] = __expf(s[nf][1] - mn0);
                s[nf][2] = __expf(s[nf][2] - mn1);
                s[nf][3] = __expf(s[nf][3] - mn1);
                rs0 += s[nf][0] + s[nf][1];
                rs1 += s[nf][2] + s[nf][3];
            }
            rs0 += __shfl_xor_sync(0xffffffffu, rs0, 1);
            rs0 += __shfl_xor_sync(0xffffffffu, rs0, 2);
            rs1 += __shfl_xor_sync(0xffffffffu, rs1, 1);
            rs1 += __shfl_xor_sync(0xffffffffu, rs1, 2);
            l0r = l0r * a0 + rs0;
            l1r = l1r * a1 + rs1;
#pragma unroll
            for (int nf = 0; nf < 16; nf++) {
                o[nf][0] *= a0; o[nf][1] *= a0;
                o[nf][2] *= a1; o[nf][3] *= a1;
            }

#pragma unroll
            for (int kf = 0; kf < 4; kf++) {
                uint32_t ph[4], pl[4];
                bf16_split2(s[2*kf][0],   s[2*kf][1],   ph[0], pl[0]);
                bf16_split2(s[2*kf][2],   s[2*kf][3],   ph[1], pl[1]);
                bf16_split2(s[2*kf+1][0], s[2*kf+1][1], ph[2], pl[2]);
                bf16_split2(s[2*kf+1][2], s[2*kf+1][3], ph[3], pl[3]);
                uint32_t voff = (uint32_t)((kf * 16 * FLD) * 2);
#pragma unroll
                for (int nf2 = 0; nf2 < 8; nf2++) {
                    uint32_t off = voff + (uint32_t)(nf2 * 32);
                    uint32_t vh0, vh1, vh2, vh3, vl0, vl1, vl2, vl3;
                    LDSM_X4T(vh0, vh1, vh2, vh3, stg + 34816u + lmV + off);
                    LDSM_X4T(vl0, vl1, vl2, vl3, stg + 52224u + lmV + off);
                    MMA16816(o[2*nf2],   ph[0], ph[1], ph[2], ph[3], vh0, vh1);
                    MMA16816(o[2*nf2],   ph[0], ph[1], ph[2], ph[3], vl0, vl1);
                    MMA16816(o[2*nf2],   pl[0], pl[1], pl[2], pl[3], vh0, vh1);
                    MMA16816(o[2*nf2+1], ph[0], ph[1], ph[2], ph[3], vh2, vh3);
                    MMA16816(o[2*nf2+1], ph[0], ph[1], ph[2], ph[3], vl2, vl3);
                    MMA16816(o[2*nf2+1], pl[0], pl[1], pl[2], pl[3], vh2, vh3);
                }
            }
        }
        __syncthreads();
    }

    // ---- epilogue: write y directly as bf16 hi/lo split ----
    const int b = bh >> 4, h = bh & 15;
    const int row0 = qbase + w * 16 + g;
    const float inv0 = 1.0f / l0r, inv1 = 1.0f / l1r;
    size_t y0off = ((size_t)(b * SEQ + row0)) * NEMBD + h * DH;
    size_t y1off = ((size_t)(b * SEQ + row0 + 8)) * NEMBD + h * DH;
#pragma unroll
    for (int nf = 0; nf < 16; nf++) {
        int col = 8 * nf + 2 * t;
        uint32_t h0, l0, h1, l1;
        bf16_split2(o[nf][0] * inv0, o[nf][1] * inv0, h0, l0);
        bf16_split2(o[nf][2] * inv1, o[nf][3] * inv1, h1, l1);
        *(uint32_t*)(Yh + y0off + col) = h0;
        *(uint32_t*)(Yl + y0off + col) = l0;
        *(uint32_t*)(Yh + y1off + col) = h1;
        *(uint32_t*)(Yl + y1off + col) = l1;
    }
}

// ================= launch =====================================================
extern "C" void kernel_launch(void* const* d_in, const int* in_sizes, int n_in,
                              void* d_out, int out_size) {
    const float* x      = (const float*)d_in[0];
    const float* w_qkv  = (const float*)d_in[1];
    const float* w_proj = (const float*)d_in[2];
    float* out = (float*)d_out;

    float *qkv, *q, *gc, *gs;
    __nv_bfloat16 *khi, *klo, *vhi, *vlo, *xhi, *xlo, *wqh, *wql, *wph, *wpl, *yhi, *ylo;
    cudaGetSymbolAddress((void**)&qkv, g_qkv);
    cudaGetSymbolAddress((void**)&q, g_q);
    cudaGetSymbolAddress((void**)&khi, g_khi);
    cudaGetSymbolAddress((void**)&klo, g_klo);
    cudaGetSymbolAddress((void**)&vhi, g_vhi);
    cudaGetSymbolAddress((void**)&vlo, g_vlo);
    cudaGetSymbolAddress((void**)&xhi, g_xhi);
    cudaGetSymbolAddress((void**)&xlo, g_xlo);
    cudaGetSymbolAddress((void**)&wqh, g_wqh);
    cudaGetSymbolAddress((void**)&wql, g_wql);
    cudaGetSymbolAddress((void**)&wph, g_wph);
    cudaGetSymbolAddress((void**)&wpl, g_wpl);
    cudaGetSymbolAddress((void**)&yhi, g_yhi);
    cudaGetSymbolAddress((void**)&ylo, g_ylo);
    cudaGetSymbolAddress((void**)&gc, g_cos);
    cudaGetSymbolAddress((void**)&gs, g_sin);

    // 1) RoPE tables + operand splits
    rope_table_kernel<<<(SEQ * 64 + 255) / 256, 256>>>(gc, gs);
    {
        long long n4;
        n4 = (long long)MROWS * NEMBD / 4;
        split_kernel<<<(unsigned)((n4 + 255) / 256), 256>>>(x, xhi, xlo, n4);
        n4 = (long long)QKV_N * NEMBD / 4;
        split_kernel<<<(unsigned)((n4 + 255) / 256), 256>>>(w_qkv, wqh, wql, n4);
        n4 = (long long)NEMBD * NEMBD / 4;
        split_kernel<<<(unsigned)((n4 + 255) / 256), 256>>>(w_proj, wph, wpl, n4);
    }

    // 2) QKV projection (bf16 HMMA, double-buffered, ldmatrix)
    cudaFuncSetAttribute(gemm_bf16_kernel,
                         cudaFuncAttributeMaxDynamicSharedMemorySize, GEMM_SMEM);
    gemm_bf16_kernel<<<dim3(QKV_N / 128, MROWS / 128), 256, GEMM_SMEM>>>(
        xhi, xlo, wqh, wql, qkv, MROWS, QKV_N, NEMBD);

    // 3) RoPE + transpose + K/V pre-split
    {
        long long total = (long long)BHN * SEQ * DH;
        rope_apply_kernel<<<(unsigned)((total + 255) / 256), 256>>>(
            qkv, gc, gs, q, khi, klo, vhi, vlo);
    }

    // 4) flash attention (HMMA) -> y split
    cudaFuncSetAttribute(flash_mma_kernel,
                         cudaFuncAttributeMaxDynamicSharedMemorySize, FA2_SMEM);
    flash_mma_kernel<<<dim3(SEQ / FBQ, BHN), 256, FA2_SMEM>>>(
        q, khi, klo, vhi, vlo, yhi, ylo);

    // 5) output projection (bf16 HMMA)
    gemm_bf16_kernel<<<dim3(NEMBD / 128, MROWS / 128), 256, GEMM_SMEM>>>(
        yhi, ylo, wph, wpl, out, MROWS, NEMBD, NEMBD);
}

// round 7
// speedup vs baseline: 1.0258x; 1.0258x over previous
#include <cuda_runtime.h>
#include <cuda_bf16.h>
#include <math.h>
#include <stdint.h>

// ---------------- problem constants ----------------
#define NEMBD   2048
#define NH      16
#define DH      128
#define BATCH   2
#define SEQ     2048
#define MROWS   (BATCH*SEQ)     // 4096
#define QKV_N   (3*NEMBD)       // 6144
#define BHN     (BATCH*NH)      // 32

// ---------------- scratch (device globals, no runtime allocs) ----------------
__device__ float g_qkv[(size_t)MROWS * QKV_N];
__device__ float g_q[(size_t)BHN*SEQ*DH];
__device__ __nv_bfloat16 g_khi[(size_t)BHN*SEQ*DH];
__device__ __nv_bfloat16 g_klo[(size_t)BHN*SEQ*DH];
__device__ __nv_bfloat16 g_vhi[(size_t)BHN*SEQ*DH];
__device__ __nv_bfloat16 g_vlo[(size_t)BHN*SEQ*DH];
__device__ __nv_bfloat16 g_xhi[(size_t)MROWS*NEMBD];
__device__ __nv_bfloat16 g_xlo[(size_t)MROWS*NEMBD];
__device__ __nv_bfloat16 g_wqh[(size_t)QKV_N*NEMBD];
__device__ __nv_bfloat16 g_wql[(size_t)QKV_N*NEMBD];
__device__ __nv_bfloat16 g_wph[(size_t)NEMBD*NEMBD];
__device__ __nv_bfloat16 g_wpl[(size_t)NEMBD*NEMBD];
__device__ __nv_bfloat16 g_yhi[(size_t)MROWS*NEMBD];
__device__ __nv_bfloat16 g_ylo[(size_t)MROWS*NEMBD];
__device__ float g_cos[SEQ*64];
__device__ float g_sin[SEQ*64];

// ================= common asm helpers =================
#define MMA16816(d, a0, a1, a2, a3, b0, b1)                                \
    asm volatile(                                                          \
        "mma.sync.aligned.m16n8k16.row.col.f32.bf16.bf16.f32 "             \
        "{%0,%1,%2,%3}, {%4,%5,%6,%7}, {%8,%9}, {%0,%1,%2,%3};"            \
        : "+f"((d)[0]), "+f"((d)[1]), "+f"((d)[2]), "+f"((d)[3])           \
        : "r"(a0), "r"(a1), "r"(a2), "r"(a3), "r"(b0), "r"(b1))

#define LDSM_X4(r0, r1, r2, r3, addr)                                       \
    asm volatile("ldmatrix.sync.aligned.m8n8.x4.shared.b16 "                \
                 "{%0,%1,%2,%3}, [%4];"                                     \
                 : "=r"(r0), "=r"(r1), "=r"(r2), "=r"(r3) : "r"(addr))

#define LDSM_X4T(r0, r1, r2, r3, addr)                                      \
    asm volatile("ldmatrix.sync.aligned.m8n8.x4.trans.shared.b16 "          \
                 "{%0,%1,%2,%3}, [%4];"                                     \
                 : "=r"(r0), "=r"(r1), "=r"(r2), "=r"(r3) : "r"(addr))

#define CP_ASYNC16(dst, src)                                                \
    asm volatile("cp.async.cg.shared.global [%0], [%1], 16;"                \
                 :: "r"(dst), "l"(src))
#define CP_COMMIT() asm volatile("cp.async.commit_group;" ::: "memory")
#define CP_WAIT1()  asm volatile("cp.async.wait_group 1;" ::: "memory")
#define CP_WAIT0()  asm volatile("cp.async.wait_group 0;" ::: "memory")

__device__ __forceinline__ uint32_t smem_u32(const void* p) {
    uint32_t a;
    asm("{ .reg .u64 t; cvta.to.shared.u64 t, %1; cvt.u32.u64 %0, t; }"
        : "=r"(a) : "l"(p));
    return a;
}

__device__ __forceinline__ void bf16_split2(float x, float y,
                                            uint32_t& hi, uint32_t& lo) {
    __nv_bfloat162 h = __floats2bfloat162_rn(x, y);
    float rx = x - __bfloat162float(__low2bfloat16(h));
    float ry = y - __bfloat162float(__high2bfloat16(h));
    __nv_bfloat162 l = __floats2bfloat162_rn(rx, ry);
    hi = *(uint32_t*)&h;
    lo = *(uint32_t*)&l;
}

// ================= RoPE tables (fp64 angles) =================
__global__ void rope_table_kernel(float* gcos, float* gsin) {
    int idx = blockIdx.x * blockDim.x + threadIdx.x;
    if (idx >= SEQ * 64) return;
    int t = idx >> 6;
    int i = idx & 63;
    double freq = exp(-((double)(2 * i) / 128.0) * log(10000.0));
    double ang = (double)t * freq;
    gcos[idx] = (float)cos(ang);
    gsin[idx] = (float)sin(ang);
}

// ================= fp32 -> bf16 hi/lo split (one-shot pass) ==================
__global__ void split_kernel(const float* __restrict__ src,
                             __nv_bfloat16* __restrict__ hi,
                             __nv_bfloat16* __restrict__ lo, long long n4) {
    long long i = (long long)blockIdx.x * blockDim.x + threadIdx.x;
    if (i >= n4) return;
    float4 v = *(const float4*)(src + i * 4);
    uint32_t h01, l01, h23, l23;
    bf16_split2(v.x, v.y, h01, l01);
    bf16_split2(v.z, v.w, h23, l23);
    *(uint2*)(hi + i * 4) = make_uint2(h01, h23);
    *(uint2*)(lo + i * 4) = make_uint2(l01, l23);
}

// ========== bf16-split HMMA GEMM (pre-split, cp.async DB, pass-reordered) ====
// C[M,N] = (AH+AL)[M,K] * (BH+BL)[N,K]^T  (split-3 accumulate)
#define SLD 40
#define GARR 10240                 // bytes per array per stage (128 rows * 80B)
#define GSTG (4*GARR)              // 40960 B per stage
#define GEMM_SMEM (2*GSTG)         // 81920 B

__global__ __launch_bounds__(256, 2)
void gemm_bf16_kernel(const __nv_bfloat16* __restrict__ AH,
                      const __nv_bfloat16* __restrict__ AL,
                      const __nv_bfloat16* __restrict__ BH,
                      const __nv_bfloat16* __restrict__ BL,
                      float* __restrict__ C, int M, int N, int K) {
    extern __shared__ char gsm[];
    const uint32_t sb = smem_u32(gsm);

    const int tid  = threadIdx.x;
    const int warp = tid >> 5, lane = tid & 31;
    const int g = lane >> 2, t = lane & 3;
    const int wm = warp & 3, wn = warp >> 2;     // 4x2 warps; warp tile 32x64
    const int m0 = blockIdx.y * 128;
    const int n0 = blockIdx.x * 128;
    const int NT = K / 32;

    float acc[2][8][4];
#pragma unroll
    for (int mf = 0; mf < 2; mf++)
#pragma unroll
        for (int nf = 0; nf < 8; nf++)
#pragma unroll
            for (int r = 0; r < 4; r++) acc[mf][nf][r] = 0.0f;

    auto prefetch = [&](int s, int kt) {
#pragma unroll
        for (int it = 0; it < 8; it++) {
            int i = tid + it * 256;
            int arr = i >> 9;            // 0..3 : AH,AL,BH,BL
            int row = (i >> 2) & 127;
            int ch  = i & 3;
            const __nv_bfloat16* src =
                (arr == 0) ? AH + (size_t)(m0 + row) * K :
                (arr == 1) ? AL + (size_t)(m0 + row) * K :
                (arr == 2) ? BH + (size_t)(n0 + row) * K :
                             BL + (size_t)(n0 + row) * K;
            src += kt * 32 + ch * 8;
            uint32_t dst = sb + (uint32_t)(s * GSTG + arr * GARR + row * 80 + ch * 16);
            CP_ASYNC16(dst, src);
        }
    };

    prefetch(0, 0);
    CP_COMMIT();

    for (int kt = 0; kt < NT; kt++) {
        if (kt + 1 < NT) {
            prefetch((kt + 1) & 1, kt + 1);
            CP_COMMIT();
            CP_WAIT1();
        } else {
            CP_WAIT0();
        }
        __syncthreads();

        const __nv_bfloat16* AsH =
            (const __nv_bfloat16*)(gsm + (size_t)(kt & 1) * GSTG);
        const __nv_bfloat16* AsL = AsH + GARR / 2;
        const __nv_bfloat16* BsH = AsH + GARR;
        const __nv_bfloat16* BsL = AsH + 3 * GARR / 2;

#pragma unroll
        for (int kk = 0; kk < 32; kk += 16) {
            // ---- preload A frags (hi + lo) ----
            uint32_t ah[2][4], al[2][4];
#pragma unroll
            for (int mf = 0; mf < 2; mf++) {
                int r = wm * 32 + mf * 16 + g;
                const __nv_bfloat16* ph = &AsH[r * SLD + kk + 2 * t];
                ah[mf][0] = *(const uint32_t*)ph;
                ah[mf][1] = *(const uint32_t*)(ph + 8 * SLD);
                ah[mf][2] = *(const uint32_t*)(ph + 8);
                ah[mf][3] = *(const uint32_t*)(ph + 8 * SLD + 8);
                const __nv_bfloat16* pl = &AsL[r * SLD + kk + 2 * t];
                al[mf][0] = *(const uint32_t*)pl;
                al[mf][1] = *(const uint32_t*)(pl + 8 * SLD);
                al[mf][2] = *(const uint32_t*)(pl + 8);
                al[mf][3] = *(const uint32_t*)(pl + 8 * SLD + 8);
            }
            // ---- preload all B-hi frags ----
            uint32_t bh[8][2];
#pragma unroll
            for (int nf = 0; nf < 8; nf++) {
                const __nv_bfloat16* p = &BsH[(wn * 64 + nf * 8 + g) * SLD + kk + 2 * t];
                bh[nf][0] = *(const uint32_t*)p;
                bh[nf][1] = *(const uint32_t*)(p + 8);
            }
            // ---- pass 1: Ahi * Bhi  (16 independent mma) ----
#pragma unroll
            for (int nf = 0; nf < 8; nf++)
#pragma unroll
                for (int mf = 0; mf < 2; mf++)
                    MMA16816(acc[mf][nf], ah[mf][0], ah[mf][1], ah[mf][2], ah[mf][3],
                             bh[nf][0], bh[nf][1]);
            // ---- pass 2: Alo * Bhi ----
#pragma unroll
            for (int nf = 0; nf < 8; nf++)
#pragma unroll
                for (int mf = 0; mf < 2; mf++)
                    MMA16816(acc[mf][nf], al[mf][0], al[mf][1], al[mf][2], al[mf][3],
                             bh[nf][0], bh[nf][1]);
            // ---- load B-lo frags (al/bh liveness ends above) ----
            uint32_t bl[8][2];
#pragma unroll
            for (int nf = 0; nf < 8; nf++) {
                const __nv_bfloat16* p = &BsL[(wn * 64 + nf * 8 + g) * SLD + kk + 2 * t];
                bl[nf][0] = *(const uint32_t*)p;
                bl[nf][1] = *(const uint32_t*)(p + 8);
            }
            // ---- pass 3: Ahi * Blo ----
#pragma unroll
            for (int nf = 0; nf < 8; nf++)
#pragma unroll
                for (int mf = 0; mf < 2; mf++)
                    MMA16816(acc[mf][nf], ah[mf][0], ah[mf][1], ah[mf][2], ah[mf][3],
                             bl[nf][0], bl[nf][1]);
        }
        __syncthreads();
    }

#pragma unroll
    for (int mf = 0; mf < 2; mf++) {
        int r0 = m0 + wm * 32 + mf * 16 + g;
#pragma unroll
        for (int nf = 0; nf < 8; nf++) {
            int col = n0 + wn * 64 + nf * 8 + 2 * t;
            float* p0 = C + (size_t)r0 * N + col;
            float* p1 = C + (size_t)(r0 + 8) * N + col;
            *(float2*)p0 = make_float2(acc[mf][nf][0], acc[mf][nf][1]);
            *(float2*)p1 = make_float2(acc[mf][nf][2], acc[mf][nf][3]);
        }
    }
}

// ======== RoPE apply + transpose; emit Q fp32 and K/V bf16 hi/lo =============
__global__ void rope_apply_kernel(const float* __restrict__ qkv,
                                  const float* __restrict__ gcos,
                                  const float* __restrict__ gsin,
                                  float* __restrict__ q,
                                  __nv_bfloat16* __restrict__ khi,
                                  __nv_bfloat16* __restrict__ klo,
                                  __nv_bfloat16* __restrict__ vhi,
                                  __nv_bfloat16* __restrict__ vlo) {
    long long idx = (long long)blockIdx.x * blockDim.x + threadIdx.x;
    const long long total = (long long)BHN * SEQ * DH;
    if (idx >= total) return;
    int d  = (int)(idx & 127);
    int t  = (int)((idx >> 7) & (SEQ - 1));
    int bh = (int)(idx >> 18);
    int b  = bh >> 4;
    int h  = bh & 15;

    size_t base = ((size_t)(b * SEQ + t)) * QKV_N + (size_t)h * DH;
    float qv = qkv[base + d];
    float kv = qkv[base + NEMBD + d];
    float vv = qkv[base + 2 * NEMBD + d];

    int ci = d & 63;
    float c = gcos[t * 64 + ci];
    float s = gsin[t * 64 + ci];
    float qr, kr;
    if (d < 64) {
        qr = -qkv[base + d + 64];
        kr = -qkv[base + NEMBD + d + 64];
    } else {
        qr = qkv[base + d - 64];
        kr = qkv[base + NEMBD + d - 64];
    }

    size_t o = ((size_t)bh * SEQ + t) * DH + d;
    q[o] = qv * c + qr * s;

    float kval = kv * c + kr * s;
    __nv_bfloat16 kh = __float2bfloat16(kval);
    khi[o] = kh;
    klo[o] = __float2bfloat16(kval - __bfloat162float(kh));

    __nv_bfloat16 vh = __float2bfloat16(vv);
    vhi[o] = vh;
    vlo[o] = __float2bfloat16(vv - __bfloat162float(vh));
}

// ================= flash attention on HMMA (bf16 split-3) ====================
#define FBQ 128
#define FBK 64
#define FLD 136
#define STG_B (4 * 17408)
#define FA2_SMEM (2 * STG_B)

__global__ __launch_bounds__(256, 1)
void flash_mma_kernel(const float* __restrict__ Qg,
                      const __nv_bfloat16* __restrict__ KH,
                      const __nv_bfloat16* __restrict__ KL,
                      const __nv_bfloat16* __restrict__ VH,
                      const __nv_bfloat16* __restrict__ VL,
                      __nv_bfloat16* __restrict__ Yh,
                      __nv_bfloat16* __restrict__ Yl) {
    extern __shared__ char smc[];
    const uint32_t sbase = smem_u32(smc);

    const int tid  = threadIdx.x;
    const int w    = tid >> 5, lane = tid & 31;
    const int g    = lane >> 2, t = lane & 3;
    const int qi   = gridDim.x - 1 - blockIdx.x;
    const int bh   = blockIdx.y;
    const int qbase = qi * FBQ;
    const int rowmax_w = qbase + w * 16 + 15;

    const size_t bhoff = (size_t)bh * SEQ * DH;

    const float scale = 0.08838834764831845f;
    uint32_t qh[8][4], ql[8][4];
    {
        const float* q0 = Qg + bhoff + (size_t)(qbase + w * 16 + g) * DH;
        const float* q1 = q0 + 8 * DH;
#pragma unroll
        for (int kf = 0; kf < 8; kf++) {
            float2 v00 = *(const float2*)(q0 + 16 * kf + 2 * t);
            float2 v10 = *(const float2*)(q1 + 16 * kf + 2 * t);
            float2 v01 = *(const float2*)(q0 + 16 * kf + 2 * t + 8);
            float2 v11 = *(const float2*)(q1 + 16 * kf + 2 * t + 8);
            bf16_split2(v00.x * scale, v00.y * scale, qh[kf][0], ql[kf][0]);
            bf16_split2(v10.x * scale, v10.y * scale, qh[kf][1], ql[kf][1]);
            bf16_split2(v01.x * scale, v01.y * scale, qh[kf][2], ql[kf][2]);
            bf16_split2(v11.x * scale, v11.y * scale, qh[kf][3], ql[kf][3]);
        }
    }

    const uint32_t lmK = (uint32_t)(((lane & 7) * FLD + (lane >> 3) * 8) * 2);
    const uint32_t lmV = (uint32_t)((((lane & 7) + ((lane >> 3) & 1) * 8) * FLD
                                     + (lane >> 4) * 8) * 2);

    float m0r = -1e30f, m1r = -1e30f, l0r = 0.0f, l1r = 0.0f;
    float o[16][4];
#pragma unroll
    for (int nf = 0; nf < 16; nf++)
#pragma unroll
        for (int r = 0; r < 4; r++) o[nf][r] = 0.0f;

    const int nkt = 2 * qi + 2;

    auto prefetch = [&](int s, int kt) {
        const int kb = kt * FBK;
        const __nv_bfloat16* srcs[4] = {
            KH + bhoff + (size_t)kb * DH, KL + bhoff + (size_t)kb * DH,
            VH + bhoff + (size_t)kb * DH, VL + bhoff + (size_t)kb * DH };
        uint32_t dst0 = sbase + (uint32_t)s * STG_B;
#pragma unroll
        for (int it = 0; it < 16; it++) {
            int i = tid + it * 256;
            int arr = i >> 10, key = (i >> 4) & 63, ch = i & 15;
            const __nv_bfloat16* src = srcs[arr] + key * DH + ch * 8;
            uint32_t dst = dst0 + (uint32_t)(arr * 17408 + key * 272 + ch * 16);
            CP_ASYNC16(dst, src);
        }
    };

    prefetch(0, 0);
    CP_COMMIT();

    for (int kt = 0; kt < nkt; kt++) {
        if (kt + 1 < nkt) {
            prefetch((kt + 1) & 1, kt + 1);
            CP_COMMIT();
            CP_WAIT1();
        } else {
            CP_WAIT0();
        }
        __syncthreads();

        const int kbase = kt * FBK;
        const bool active = (kbase <= rowmax_w);
        if (active) {
            const uint32_t stg = sbase + (uint32_t)(kt & 1) * STG_B;

            float s[8][4];
#pragma unroll
            for (int nf = 0; nf < 8; nf++)
#pragma unroll
                for (int r = 0; r < 4; r++) s[nf][r] = 0.0f;

#pragma unroll
            for (int kf2 = 0; kf2 < 4; kf2++) {
#pragma unroll
                for (int nf = 0; nf < 8; nf++) {
                    uint32_t off = (uint32_t)((nf * 8 * FLD + kf2 * 32) * 2);
                    uint32_t bh0, bh1, bh2, bh3, bl0, bl1, bl2, bl3;
                    LDSM_X4(bh0, bh1, bh2, bh3, stg + lmK + off);
                    LDSM_X4(bl0, bl1, bl2, bl3, stg + 17408u + lmK + off);
                    MMA16816(s[nf], qh[2*kf2][0], qh[2*kf2][1], qh[2*kf2][2], qh[2*kf2][3], bh0, bh1);
                    MMA16816(s[nf], qh[2*kf2][0], qh[2*kf2][1], qh[2*kf2][2], qh[2*kf2][3], bl0, bl1);
                    MMA16816(s[nf], ql[2*kf2][0], ql[2*kf2][1], ql[2*kf2][2], ql[2*kf2][3], bh0, bh1);
                    MMA16816(s[nf], qh[2*kf2+1][0], qh[2*kf2+1][1], qh[2*kf2+1][2], qh[2*kf2+1][3], bh2, bh3);
                    MMA16816(s[nf], qh[2*kf2+1][0], qh[2*kf2+1][1], qh[2*kf2+1][2], qh[2*kf2+1][3], bl2, bl3);
                    MMA16816(s[nf], ql[2*kf2+1][0], ql[2*kf2+1][1], ql[2*kf2+1][2], ql[2*kf2+1][3], bh2, bh3);
                }
            }

            const int row0 = qbase + w * 16 + g;
            const int row1 = row0 + 8;
            if (kbase + FBK - 1 > qbase + w * 16) {
#pragma unroll
                for (int nf = 0; nf < 8; nf++) {
                    int c0 = kbase + 8 * nf + 2 * t;
                    if (c0 > row0)     s[nf][0] = -1e30f;
                    if (c0 + 1 > row0) s[nf][1] = -1e30f;
                    if (c0 > row1)     s[nf][2] = -1e30f;
                    if (c0 + 1 > row1) s[nf][3] = -1e30f;
                }
            }

            float mx0 = -1e30f, mx1 = -1e30f;
#pragma unroll
            for (int nf = 0; nf < 8; nf++) {
                mx0 = fmaxf(mx0, fmaxf(s[nf][0], s[nf][1]));
                mx1 = fmaxf(mx1, fmaxf(s[nf][2], s[nf][3]));
            }
            mx0 = fmaxf(mx0, __shfl_xor_sync(0xffffffffu, mx0, 1));
            mx0 = fmaxf(mx0, __shfl_xor_sync(0xffffffffu, mx0, 2));
            mx1 = fmaxf(mx1, __shfl_xor_sync(0xffffffffu, mx1, 1));
            mx1 = fmaxf(mx1, __shfl_xor_sync(0xffffffffu, mx1, 2));
            float mn0 = fmaxf(m0r, mx0), mn1 = fmaxf(m1r, mx1);
            float a0 = __expf(m0r - mn0), a1 = __expf(m1r - mn1);
            m0r = mn0; m1r = mn1;
            float rs0 = 0.0f, rs1 = 0.0f;
#pragma unroll
            for (int nf = 0; nf < 8; nf++) {
                s[nf][0] = __expf(s[nf][0] - mn0);
                s[nf][1] = __expf(s[nf][1] - mn0);
                s[nf][2] = __expf(s[nf][2] - mn1);
                s[nf][3] = __expf(s[nf][3] - mn1);
                rs0 += s[nf][0] + s[nf][1];
                rs1 += s[nf][2] + s[nf][3];
            }
            rs0 += __shfl_xor_sync(0xffffffffu, rs0, 1);
            rs0 += __shfl_xor_sync(0xffffffffu, rs0, 2);
            rs1 += __shfl_xor_sync(0xffffffffu, rs1, 1);
            rs1 += __shfl_xor_sync(0xffffffffu, rs1, 2);
            l0r = l0r * a0 + rs0;
            l1r = l1r * a1 + rs1;
#pragma unroll
            for (int nf = 0; nf < 16; nf++) {
                o[nf][0] *= a0; o[nf][1] *= a0;
                o[nf][2] *= a1; o[nf][3] *= a1;
            }

#pragma unroll
            for (int kf = 0; kf < 4; kf++) {
                uint32_t ph[4], pl[4];
                bf16_split2(s[2*kf][0],   s[2*kf][1],   ph[0], pl[0]);
                bf16_split2(s[2*kf][2],   s[2*kf][3],   ph[1], pl[1]);
                bf16_split2(s[2*kf+1][0], s[2*kf+1][1], ph[2], pl[2]);
                bf16_split2(s[2*kf+1][2], s[2*kf+1][3], ph[3], pl[3]);
                uint32_t voff = (uint32_t)((kf * 16 * FLD) * 2);
#pragma unroll
                for (int nf2 = 0; nf2 < 8; nf2++) {
                    uint32_t off = voff + (uint32_t)(nf2 * 32);
                    uint32_t vh0, vh1, vh2, vh3, vl0, vl1, vl2, vl3;
                    LDSM_X4T(vh0, vh1, vh2, vh3, stg + 34816u + lmV + off);
                    LDSM_X4T(vl0, vl1, vl2, vl3, stg + 52224u + lmV + off);
                    MMA16816(o[2*nf2],   ph[0], ph[1], ph[2], ph[3], vh0, vh1);
                    MMA16816(o[2*nf2],   ph[0], ph[1], ph[2], ph[3], vl0, vl1);
                    MMA16816(o[2*nf2],   pl[0], pl[1], pl[2], pl[3], vh0, vh1);
                    MMA16816(o[2*nf2+1], ph[0], ph[1], ph[2], ph[3], vh2, vh3);
                    MMA16816(o[2*nf2+1], ph[0], ph[1], ph[2], ph[3], vl2, vl3);
                    MMA16816(o[2*nf2+1], pl[0], pl[1], pl[2], pl[3], vh2, vh3);
                }
            }
        }
        __syncthreads();
    }

    // ---- epilogue: write y directly as bf16 hi/lo split ----
    const int b = bh >> 4, h = bh & 15;
    const int row0 = qbase + w * 16 + g;
    const float inv0 = 1.0f / l0r, inv1 = 1.0f / l1r;
    size_t y0off = ((size_t)(b * SEQ + row0)) * NEMBD + h * DH;
    size_t y1off = ((size_t)(b * SEQ + row0 + 8)) * NEMBD + h * DH;
#pragma unroll
    for (int nf = 0; nf < 16; nf++) {
        int col = 8 * nf + 2 * t;
        uint32_t h0, l0, h1, l1;
        bf16_split2(o[nf][0] * inv0, o[nf][1] * inv0, h0, l0);
        bf16_split2(o[nf][2] * inv1, o[nf][3] * inv1, h1, l1);
        *(uint32_t*)(Yh + y0off + col) = h0;
        *(uint32_t*)(Yl + y0off + col) = l0;
        *(uint32_t*)(Yh + y1off + col) = h1;
        *(uint32_t*)(Yl + y1off + col) = l1;
    }
}

// ================= launch =====================================================
extern "C" void kernel_launch(void* const* d_in, const int* in_sizes, int n_in,
                              void* d_out, int out_size) {
    const float* x      = (const float*)d_in[0];
    const float* w_qkv  = (const float*)d_in[1];
    const float* w_proj = (const float*)d_in[2];
    float* out = (float*)d_out;

    float *qkv, *q, *gc, *gs;
    __nv_bfloat16 *khi, *klo, *vhi, *vlo, *xhi, *xlo, *wqh, *wql, *wph, *wpl, *yhi, *ylo;
    cudaGetSymbolAddress((void**)&qkv, g_qkv);
    cudaGetSymbolAddress((void**)&q, g_q);
    cudaGetSymbolAddress((void**)&khi, g_khi);
    cudaGetSymbolAddress((void**)&klo, g_klo);
    cudaGetSymbolAddress((void**)&vhi, g_vhi);
    cudaGetSymbolAddress((void**)&vlo, g_vlo);
    cudaGetSymbolAddress((void**)&xhi, g_xhi);
    cudaGetSymbolAddress((void**)&xlo, g_xlo);
    cudaGetSymbolAddress((void**)&wqh, g_wqh);
    cudaGetSymbolAddress((void**)&wql, g_wql);
    cudaGetSymbolAddress((void**)&wph, g_wph);
    cudaGetSymbolAddress((void**)&wpl, g_wpl);
    cudaGetSymbolAddress((void**)&yhi, g_yhi);
    cudaGetSymbolAddress((void**)&ylo, g_ylo);
    cudaGetSymbolAddress((void**)&gc, g_cos);
    cudaGetSymbolAddress((void**)&gs, g_sin);

    // 1) RoPE tables + operand splits
    rope_table_kernel<<<(SEQ * 64 + 255) / 256, 256>>>(gc, gs);
    {
        long long n4;
        n4 = (long long)MROWS * NEMBD / 4;
        split_kernel<<<(unsigned)((n4 + 255) / 256), 256>>>(x, xhi, xlo, n4);
        n4 = (long long)QKV_N * NEMBD / 4;
        split_kernel<<<(unsigned)((n4 + 255) / 256), 256>>>(w_qkv, wqh, wql, n4);
        n4 = (long long)NEMBD * NEMBD / 4;
        split_kernel<<<(unsigned)((n4 + 255) / 256), 256>>>(w_proj, wph, wpl, n4);
    }

    // 2) QKV projection (bf16 HMMA, double-buffered, pass-reordered)
    cudaFuncSetAttribute(gemm_bf16_kernel,
                         cudaFuncAttributeMaxDynamicSharedMemorySize, GEMM_SMEM);
    gemm_bf16_kernel<<<dim3(QKV_N / 128, MROWS / 128), 256, GEMM_SMEM>>>(
        xhi, xlo, wqh, wql, qkv, MROWS, QKV_N, NEMBD);

    // 3) RoPE + transpose + K/V pre-split
    {
        long long total = (long long)BHN * SEQ * DH;
        rope_apply_kernel<<<(unsigned)((total + 255) / 256), 256>>>(
            qkv, gc, gs, q, khi, klo, vhi, vlo);
    }

    // 4) flash attention (HMMA) -> y split
    cudaFuncSetAttribute(flash_mma_kernel,
                         cudaFuncAttributeMaxDynamicSharedMemorySize, FA2_SMEM);
    flash_mma_kernel<<<dim3(SEQ / FBQ, BHN), 256, FA2_SMEM>>>(
        q, khi, klo, vhi, vlo, yhi, ylo);

    // 5) output projection (bf16 HMMA)
    gemm_bf16_kernel<<<dim3(NEMBD / 128, MROWS / 128), 256, GEMM_SMEM>>>(
        yhi, ylo, wph, wpl, out, MROWS, NEMBD, NEMBD);
}

// round 8
// speedup vs baseline: 1.4183x; 1.3826x over previous
#include <cuda_runtime.h>
#include <cuda_fp16.h>
#include <math.h>
#include <stdint.h>

// ---------------- problem constants ----------------
#define NEMBD   2048
#define NH      16
#define DH      128
#define BATCH   2
#define SEQ     2048
#define MROWS   (BATCH*SEQ)     // 4096
#define QKV_N   (3*NEMBD)       // 6144
#define BHN     (BATCH*NH)      // 32

// ---------------- scratch (device globals, no runtime allocs) ----------------
__device__ float g_qkv[(size_t)MROWS * QKV_N];
__device__ float g_q[(size_t)BHN*SEQ*DH];
__device__ __half g_kh[(size_t)BHN*SEQ*DH];
__device__ __half g_vh[(size_t)BHN*SEQ*DH];
__device__ __half g_xhi[(size_t)MROWS*NEMBD];
__device__ __half g_xlo[(size_t)MROWS*NEMBD];
__device__ __half g_wq[(size_t)QKV_N*NEMBD];
__device__ __half g_wp[(size_t)NEMBD*NEMBD];
__device__ __half g_yhi[(size_t)MROWS*NEMBD];
__device__ __half g_ylo[(size_t)MROWS*NEMBD];
__device__ float g_cos[SEQ*64];
__device__ float g_sin[SEQ*64];

// ================= common asm helpers =================
#define MMA16816(d, a0, a1, a2, a3, b0, b1)                                \
    asm volatile(                                                          \
        "mma.sync.aligned.m16n8k16.row.col.f32.f16.f16.f32 "               \
        "{%0,%1,%2,%3}, {%4,%5,%6,%7}, {%8,%9}, {%0,%1,%2,%3};"            \
        : "+f"((d)[0]), "+f"((d)[1]), "+f"((d)[2]), "+f"((d)[3])           \
        : "r"(a0), "r"(a1), "r"(a2), "r"(a3), "r"(b0), "r"(b1))

#define LDSM_X4(r0, r1, r2, r3, addr)                                       \
    asm volatile("ldmatrix.sync.aligned.m8n8.x4.shared.b16 "                \
                 "{%0,%1,%2,%3}, [%4];"                                     \
                 : "=r"(r0), "=r"(r1), "=r"(r2), "=r"(r3) : "r"(addr))

#define LDSM_X4T(r0, r1, r2, r3, addr)                                      \
    asm volatile("ldmatrix.sync.aligned.m8n8.x4.trans.shared.b16 "          \
                 "{%0,%1,%2,%3}, [%4];"                                     \
                 : "=r"(r0), "=r"(r1), "=r"(r2), "=r"(r3) : "r"(addr))

#define CP_ASYNC16(dst, src)                                                \
    asm volatile("cp.async.cg.shared.global [%0], [%1], 16;"                \
                 :: "r"(dst), "l"(src))
#define CP_COMMIT() asm volatile("cp.async.commit_group;" ::: "memory")
#define CP_WAIT1()  asm volatile("cp.async.wait_group 1;" ::: "memory")
#define CP_WAIT0()  asm volatile("cp.async.wait_group 0;" ::: "memory")

__device__ __forceinline__ uint32_t smem_u32(const void* p) {
    uint32_t a;
    asm("{ .reg .u64 t; cvta.to.shared.u64 t, %1; cvt.u32.u64 %0, t; }"
        : "=r"(a) : "l"(p));
    return a;
}

// fp16 split: x = hi + lo, hi/lo both fp16 (11-bit mantissa each)
__device__ __forceinline__ void fp16_split2(float x, float y,
                                            uint32_t& hi, uint32_t& lo) {
    __half2 h = __floats2half2_rn(x, y);
    float rx = x - __half2float(__low2half(h));
    float ry = y - __half2float(__high2half(h));
    __half2 l = __floats2half2_rn(rx, ry);
    hi = *(uint32_t*)&h;
    lo = *(uint32_t*)&l;
}
__device__ __forceinline__ uint32_t fp16_pack2(float x, float y) {
    __half2 h = __floats2half2_rn(x, y);
    return *(uint32_t*)&h;
}

// ================= RoPE tables (fp64 angles) =================
__global__ void rope_table_kernel(float* gcos, float* gsin) {
    int idx = blockIdx.x * blockDim.x + threadIdx.x;
    if (idx >= SEQ * 64) return;
    int t = idx >> 6;
    int i = idx & 63;
    double freq = exp(-((double)(2 * i) / 128.0) * log(10000.0));
    double ang = (double)t * freq;
    gcos[idx] = (float)cos(ang);
    gsin[idx] = (float)sin(ang);
}

// ============ fp32 -> fp16 hi/lo split and plain-convert passes ==============
__global__ void split2_kernel(const float* __restrict__ src,
                              __half* __restrict__ hi,
                              __half* __restrict__ lo, long long n4) {
    long long i = (long long)blockIdx.x * blockDim.x + threadIdx.x;
    if (i >= n4) return;
    float4 v = *(const float4*)(src + i * 4);
    uint32_t h01, l01, h23, l23;
    fp16_split2(v.x, v.y, h01, l01);
    fp16_split2(v.z, v.w, h23, l23);
    *(uint2*)(hi + i * 4) = make_uint2(h01, h23);
    *(uint2*)(lo + i * 4) = make_uint2(l01, l23);
}
__global__ void cvt_kernel(const float* __restrict__ src,
                           __half* __restrict__ dst, long long n4) {
    long long i = (long long)blockIdx.x * blockDim.x + threadIdx.x;
    if (i >= n4) return;
    float4 v = *(const float4*)(src + i * 4);
    *(uint2*)(dst + i * 4) = make_uint2(fp16_pack2(v.x, v.y), fp16_pack2(v.z, v.w));
}

// ===== fp16 split-2 HMMA GEMM: C[M,N] = (AH+AL)[M,K] * W[N,K]^T ==============
#define SLD 40
#define GARR 10240                 // bytes per array per stage (128 rows * 80B)
#define GSTG (3*GARR)              // AH, AL, W = 30720 B per stage
#define GEMM_SMEM (2*GSTG)         // 61440 B

__global__ __launch_bounds__(256, 2)
void gemm_fp16_kernel(const __half* __restrict__ AH,
                      const __half* __restrict__ AL,
                      const __half* __restrict__ W,
                      float* __restrict__ C, int M, int N, int K) {
    extern __shared__ char gsm[];
    const uint32_t sb = smem_u32(gsm);

    const int tid  = threadIdx.x;
    const int warp = tid >> 5, lane = tid & 31;
    const int g = lane >> 2, t = lane & 3;
    const int wm = warp & 3, wn = warp >> 2;     // 4x2 warps; warp tile 32x64
    const int m0 = blockIdx.y * 128;
    const int n0 = blockIdx.x * 128;
    const int NT = K / 32;

    float acc[2][8][4];
#pragma unroll
    for (int mf = 0; mf < 2; mf++)
#pragma unroll
        for (int nf = 0; nf < 8; nf++)
#pragma unroll
            for (int r = 0; r < 4; r++) acc[mf][nf][r] = 0.0f;

    auto prefetch = [&](int s, int kt) {
#pragma unroll
        for (int it = 0; it < 6; it++) {
            int i = tid + it * 256;
            int arr = i >> 9;            // 0..2 : AH, AL, W
            int row = (i >> 2) & 127;
            int ch  = i & 3;
            const __half* src =
                (arr == 0) ? AH + (size_t)(m0 + row) * K :
                (arr == 1) ? AL + (size_t)(m0 + row) * K :
                             W  + (size_t)(n0 + row) * K;
            src += kt * 32 + ch * 8;
            uint32_t dst = sb + (uint32_t)(s * GSTG + arr * GARR + row * 80 + ch * 16);
            CP_ASYNC16(dst, src);
        }
    };

    prefetch(0, 0);
    CP_COMMIT();

    for (int kt = 0; kt < NT; kt++) {
        if (kt + 1 < NT) {
            prefetch((kt + 1) & 1, kt + 1);
            CP_COMMIT();
            CP_WAIT1();
        } else {
            CP_WAIT0();
        }
        __syncthreads();

        const __half* AsH = (const __half*)(gsm + (size_t)(kt & 1) * GSTG);
        const __half* AsL = AsH + GARR / 2;
        const __half* Ws  = AsH + GARR;

#pragma unroll
        for (int kk = 0; kk < 32; kk += 16) {
            uint32_t ah[2][4], al[2][4];
#pragma unroll
            for (int mf = 0; mf < 2; mf++) {
                int r = wm * 32 + mf * 16 + g;
                const __half* ph = &AsH[r * SLD + kk + 2 * t];
                ah[mf][0] = *(const uint32_t*)ph;
                ah[mf][1] = *(const uint32_t*)(ph + 8 * SLD);
                ah[mf][2] = *(const uint32_t*)(ph + 8);
                ah[mf][3] = *(const uint32_t*)(ph + 8 * SLD + 8);
                const __half* pl = &AsL[r * SLD + kk + 2 * t];
                al[mf][0] = *(const uint32_t*)pl;
                al[mf][1] = *(const uint32_t*)(pl + 8 * SLD);
                al[mf][2] = *(const uint32_t*)(pl + 8);
                al[mf][3] = *(const uint32_t*)(pl + 8 * SLD + 8);
            }
#pragma unroll
            for (int nf = 0; nf < 8; nf++) {
                const __half* p = &Ws[(wn * 64 + nf * 8 + g) * SLD + kk + 2 * t];
                uint32_t w0 = *(const uint32_t*)p;
                uint32_t w1 = *(const uint32_t*)(p + 8);
#pragma unroll
                for (int mf = 0; mf < 2; mf++) {
                    MMA16816(acc[mf][nf], ah[mf][0], ah[mf][1], ah[mf][2], ah[mf][3], w0, w1);
                    MMA16816(acc[mf][nf], al[mf][0], al[mf][1], al[mf][2], al[mf][3], w0, w1);
                }
            }
        }
        __syncthreads();
    }

#pragma unroll
    for (int mf = 0; mf < 2; mf++) {
        int r0 = m0 + wm * 32 + mf * 16 + g;
#pragma unroll
        for (int nf = 0; nf < 8; nf++) {
            int col = n0 + wn * 64 + nf * 8 + 2 * t;
            float* p0 = C + (size_t)r0 * N + col;
            float* p1 = C + (size_t)(r0 + 8) * N + col;
            *(float2*)p0 = make_float2(acc[mf][nf][0], acc[mf][nf][1]);
            *(float2*)p1 = make_float2(acc[mf][nf][2], acc[mf][nf][3]);
        }
    }
}

// ======== RoPE apply + transpose; emit Q fp32, K/V plain fp16 ================
__global__ void rope_apply_kernel(const float* __restrict__ qkv,
                                  const float* __restrict__ gcos,
                                  const float* __restrict__ gsin,
                                  float* __restrict__ q,
                                  __half* __restrict__ kh,
                                  __half* __restrict__ vh) {
    long long idx = (long long)blockIdx.x * blockDim.x + threadIdx.x;
    const long long total = (long long)BHN * SEQ * DH;
    if (idx >= total) return;
    int d  = (int)(idx & 127);
    int t  = (int)((idx >> 7) & (SEQ - 1));
    int bh = (int)(idx >> 18);
    int b  = bh >> 4;
    int h  = bh & 15;

    size_t base = ((size_t)(b * SEQ + t)) * QKV_N + (size_t)h * DH;
    float qv = qkv[base + d];
    float kv = qkv[base + NEMBD + d];
    float vv = qkv[base + 2 * NEMBD + d];

    int ci = d & 63;
    float c = gcos[t * 64 + ci];
    float s = gsin[t * 64 + ci];
    float qr, kr;
    if (d < 64) {
        qr = -qkv[base + d + 64];
        kr = -qkv[base + NEMBD + d + 64];
    } else {
        qr = qkv[base + d - 64];
        kr = qkv[base + NEMBD + d - 64];
    }

    size_t o = ((size_t)bh * SEQ + t) * DH + d;
    q[o] = qv * c + qr * s;
    kh[o] = __float2half_rn(kv * c + kr * s);
    vh[o] = __float2half_rn(vv);
}

// ============ flash attention on HMMA (fp16, Q/P split-2) ====================
#define FBQ 128
#define FBK 64
#define FLD 136
#define ARRB 17408u                 // 64 rows * 272 B
#define STG_B (2 * 17408)           // K, V
#define FA2_SMEM (2 * STG_B)        // 69632 B

__global__ __launch_bounds__(256, 1)
void flash_mma_kernel(const float* __restrict__ Qg,
                      const __half* __restrict__ KH,
                      const __half* __restrict__ VH,
                      __half* __restrict__ Yh,
                      __half* __restrict__ Yl) {
    extern __shared__ char smc[];
    const uint32_t sbase = smem_u32(smc);

    const int tid  = threadIdx.x;
    const int w    = tid >> 5, lane = tid & 31;
    const int g    = lane >> 2, t = lane & 3;
    const int qi   = gridDim.x - 1 - blockIdx.x;
    const int bh   = blockIdx.y;
    const int qbase = qi * FBQ;
    const int rowmax_w = qbase + w * 16 + 15;

    const size_t bhoff = (size_t)bh * SEQ * DH;

    const float scale = 0.08838834764831845f;
    uint32_t qh[8][4], ql[8][4];
    {
        const float* q0 = Qg + bhoff + (size_t)(qbase + w * 16 + g) * DH;
        const float* q1 = q0 + 8 * DH;
#pragma unroll
        for (int kf = 0; kf < 8; kf++) {
            float2 v00 = *(const float2*)(q0 + 16 * kf + 2 * t);
            float2 v10 = *(const float2*)(q1 + 16 * kf + 2 * t);
            float2 v01 = *(const float2*)(q0 + 16 * kf + 2 * t + 8);
            float2 v11 = *(const float2*)(q1 + 16 * kf + 2 * t + 8);
            fp16_split2(v00.x * scale, v00.y * scale, qh[kf][0], ql[kf][0]);
            fp16_split2(v10.x * scale, v10.y * scale, qh[kf][1], ql[kf][1]);
            fp16_split2(v01.x * scale, v01.y * scale, qh[kf][2], ql[kf][2]);
            fp16_split2(v11.x * scale, v11.y * scale, qh[kf][3], ql[kf][3]);
        }
    }

    const uint32_t lmK = (uint32_t)(((lane & 7) * FLD + (lane >> 3) * 8) * 2);
    const uint32_t lmV = (uint32_t)((((lane & 7) + ((lane >> 3) & 1) * 8) * FLD
                                     + (lane >> 4) * 8) * 2);

    float m0r = -1e30f, m1r = -1e30f, l0r = 0.0f, l1r = 0.0f;
    float o[16][4];
#pragma unroll
    for (int nf = 0; nf < 16; nf++)
#pragma unroll
        for (int r = 0; r < 4; r++) o[nf][r] = 0.0f;

    const int nkt = 2 * qi + 2;

    auto prefetch = [&](int s, int kt) {
        const int kb = kt * FBK;
        const __half* srcs[2] = { KH + bhoff + (size_t)kb * DH,
                                  VH + bhoff + (size_t)kb * DH };
        uint32_t dst0 = sbase + (uint32_t)s * STG_B;
#pragma unroll
        for (int it = 0; it < 8; it++) {
            int i = tid + it * 256;
            int arr = i >> 10, key = (i >> 4) & 63, ch = i & 15;
            const __half* src = srcs[arr] + key * DH + ch * 8;
            uint32_t dst = dst0 + (uint32_t)(arr * ARRB + key * 272 + ch * 16);
            CP_ASYNC16(dst, src);
        }
    };

    prefetch(0, 0);
    CP_COMMIT();

    for (int kt = 0; kt < nkt; kt++) {
        if (kt + 1 < nkt) {
            prefetch((kt + 1) & 1, kt + 1);
            CP_COMMIT();
            CP_WAIT1();
        } else {
            CP_WAIT0();
        }
        __syncthreads();

        const int kbase = kt * FBK;
        const bool active = (kbase <= rowmax_w);
        if (active) {
            const uint32_t stg = sbase + (uint32_t)(kt & 1) * STG_B;

            float s[8][4];
#pragma unroll
            for (int nf = 0; nf < 8; nf++)
#pragma unroll
                for (int r = 0; r < 4; r++) s[nf][r] = 0.0f;

            // ---- S = Q K^T : Qhi*K + Qlo*K ----
#pragma unroll
            for (int kf2 = 0; kf2 < 4; kf2++) {
#pragma unroll
                for (int nf = 0; nf < 8; nf++) {
                    uint32_t off = (uint32_t)((nf * 8 * FLD + kf2 * 32) * 2);
                    uint32_t k0, k1, k2, k3;
                    LDSM_X4(k0, k1, k2, k3, stg + lmK + off);
                    MMA16816(s[nf], qh[2*kf2][0], qh[2*kf2][1], qh[2*kf2][2], qh[2*kf2][3], k0, k1);
                    MMA16816(s[nf], ql[2*kf2][0], ql[2*kf2][1], ql[2*kf2][2], ql[2*kf2][3], k0, k1);
                    MMA16816(s[nf], qh[2*kf2+1][0], qh[2*kf2+1][1], qh[2*kf2+1][2], qh[2*kf2+1][3], k2, k3);
                    MMA16816(s[nf], ql[2*kf2+1][0], ql[2*kf2+1][1], ql[2*kf2+1][2], ql[2*kf2+1][3], k2, k3);
                }
            }

            const int row0 = qbase + w * 16 + g;
            const int row1 = row0 + 8;
            if (kbase + FBK - 1 > qbase + w * 16) {
#pragma unroll
                for (int nf = 0; nf < 8; nf++) {
                    int c0 = kbase + 8 * nf + 2 * t;
                    if (c0 > row0)     s[nf][0] = -1e30f;
                    if (c0 + 1 > row0) s[nf][1] = -1e30f;
                    if (c0 > row1)     s[nf][2] = -1e30f;
                    if (c0 + 1 > row1) s[nf][3] = -1e30f;
                }
            }

            float mx0 = -1e30f, mx1 = -1e30f;
#pragma unroll
            for (int nf = 0; nf < 8; nf++) {
                mx0 = fmaxf(mx0, fmaxf(s[nf][0], s[nf][1]));
                mx1 = fmaxf(mx1, fmaxf(s[nf][2], s[nf][3]));
            }
            mx0 = fmaxf(mx0, __shfl_xor_sync(0xffffffffu, mx0, 1));
            mx0 = fmaxf(mx0, __shfl_xor_sync(0xffffffffu, mx0, 2));
            mx1 = fmaxf(mx1, __shfl_xor_sync(0xffffffffu, mx1, 1));
            mx1 = fmaxf(mx1, __shfl_xor_sync(0xffffffffu, mx1, 2));
            float mn0 = fmaxf(m0r, mx0), mn1 = fmaxf(m1r, mx1);
            float a0 = __expf(m0r - mn0), a1 = __expf(m1r - mn1);
            m0r = mn0; m1r = mn1;
            float rs0 = 0.0f, rs1 = 0.0f;
#pragma unroll
            for (int nf = 0; nf < 8; nf++) {
                s[nf][0] = __expf(s[nf][0] - mn0);
                s[nf][1] = __expf(s[nf][1] - mn0);
                s[nf][2] = __expf(s[nf][2] - mn1);
                s[nf][3] = __expf(s[nf][3] - mn1);
                rs0 += s[nf][0] + s[nf][1];
                rs1 += s[nf][2] + s[nf][3];
            }
            rs0 += __shfl_xor_sync(0xffffffffu, rs0, 1);
            rs0 += __shfl_xor_sync(0xffffffffu, rs0, 2);
            rs1 += __shfl_xor_sync(0xffffffffu, rs1, 1);
            rs1 += __shfl_xor_sync(0xffffffffu, rs1, 2);
            l0r = l0r * a0 + rs0;
            l1r = l1r * a1 + rs1;
#pragma unroll
            for (int nf = 0; nf < 16; nf++) {
                o[nf][0] *= a0; o[nf][1] *= a0;
                o[nf][2] *= a1; o[nf][3] *= a1;
            }

            // ---- O += P V : Phi*V + Plo*V ----
#pragma unroll
            for (int kf = 0; kf < 4; kf++) {
                uint32_t ph[4], pl[4];
                fp16_split2(s[2*kf][0],   s[2*kf][1],   ph[0], pl[0]);
                fp16_split2(s[2*kf][2],   s[2*kf][3],   ph[1], pl[1]);
                fp16_split2(s[2*kf+1][0], s[2*kf+1][1], ph[2], pl[2]);
                fp16_split2(s[2*kf+1][2], s[2*kf+1][3], ph[3], pl[3]);
                uint32_t voff = (uint32_t)((kf * 16 * FLD) * 2);
#pragma unroll
                for (int nf2 = 0; nf2 < 8; nf2++) {
                    uint32_t off = voff + (uint32_t)(nf2 * 32);
                    uint32_t v0, v1, v2, v3;
                    LDSM_X4T(v0, v1, v2, v3, stg + ARRB + lmV + off);
                    MMA16816(o[2*nf2],   ph[0], ph[1], ph[2], ph[3], v0, v1);
                    MMA16816(o[2*nf2],   pl[0], pl[1], pl[2], pl[3], v0, v1);
                    MMA16816(o[2*nf2+1], ph[0], ph[1], ph[2], ph[3], v2, v3);
                    MMA16816(o[2*nf2+1], pl[0], pl[1], pl[2], pl[3], v2, v3);
                }
            }
        }
        __syncthreads();
    }

    // ---- epilogue: write y directly as fp16 hi/lo split ----
    const int b = bh >> 4, h = bh & 15;
    const int row0 = qbase + w * 16 + g;
    const float inv0 = 1.0f / l0r, inv1 = 1.0f / l1r;
    size_t y0off = ((size_t)(b * SEQ + row0)) * NEMBD + h * DH;
    size_t y1off = ((size_t)(b * SEQ + row0 + 8)) * NEMBD + h * DH;
#pragma unroll
    for (int nf = 0; nf < 16; nf++) {
        int col = 8 * nf + 2 * t;
        uint32_t h0, l0, h1, l1;
        fp16_split2(o[nf][0] * inv0, o[nf][1] * inv0, h0, l0);
        fp16_split2(o[nf][2] * inv1, o[nf][3] * inv1, h1, l1);
        *(uint32_t*)(Yh + y0off + col) = h0;
        *(uint32_t*)(Yl + y0off + col) = l0;
        *(uint32_t*)(Yh + y1off + col) = h1;
        *(uint32_t*)(Yl + y1off + col) = l1;
    }
}

// ================= launch =====================================================
extern "C" void kernel_launch(void* const* d_in, const int* in_sizes, int n_in,
                              void* d_out, int out_size) {
    const float* x      = (const float*)d_in[0];
    const float* w_qkv  = (const float*)d_in[1];
    const float* w_proj = (const float*)d_in[2];
    float* out = (float*)d_out;

    float *qkv, *q, *gc, *gs;
    __half *kh, *vh, *xhi, *xlo, *wq, *wp, *yhi, *ylo;
    cudaGetSymbolAddress((void**)&qkv, g_qkv);
    cudaGetSymbolAddress((void**)&q, g_q);
    cudaGetSymbolAddress((void**)&kh, g_kh);
    cudaGetSymbolAddress((void**)&vh, g_vh);
    cudaGetSymbolAddress((void**)&xhi, g_xhi);
    cudaGetSymbolAddress((void**)&xlo, g_xlo);
    cudaGetSymbolAddress((void**)&wq, g_wq);
    cudaGetSymbolAddress((void**)&wp, g_wp);
    cudaGetSymbolAddress((void**)&yhi, g_yhi);
    cudaGetSymbolAddress((void**)&ylo, g_ylo);
    cudaGetSymbolAddress((void**)&gc, g_cos);
    cudaGetSymbolAddress((void**)&gs, g_sin);

    // 1) RoPE tables + operand conversions
    rope_table_kernel<<<(SEQ * 64 + 255) / 256, 256>>>(gc, gs);
    {
        long long n4;
        n4 = (long long)MROWS * NEMBD / 4;
        split2_kernel<<<(unsigned)((n4 + 255) / 256), 256>>>(x, xhi, xlo, n4);
        n4 = (long long)QKV_N * NEMBD / 4;
        cvt_kernel<<<(unsigned)((n4 + 255) / 256), 256>>>(w_qkv, wq, n4);
        n4 = (long long)NEMBD * NEMBD / 4;
        cvt_kernel<<<(unsigned)((n4 + 255) / 256), 256>>>(w_proj, wp, n4);
    }

    // 2) QKV projection (fp16 split-2 HMMA)
    cudaFuncSetAttribute(gemm_fp16_kernel,
                         cudaFuncAttributeMaxDynamicSharedMemorySize, GEMM_SMEM);
    gemm_fp16_kernel<<<dim3(QKV_N / 128, MROWS / 128), 256, GEMM_SMEM>>>(
        xhi, xlo, wq, qkv, MROWS, QKV_N, NEMBD);

    // 3) RoPE + transpose + K/V fp16 convert
    {
        long long total = (long long)BHN * SEQ * DH;
        rope_apply_kernel<<<(unsigned)((total + 255) / 256), 256>>>(
            qkv, gc, gs, q, kh, vh);
    }

    // 4) flash attention (fp16 HMMA) -> y split
    cudaFuncSetAttribute(flash_mma_kernel,
                         cudaFuncAttributeMaxDynamicSharedMemorySize, FA2_SMEM);
    flash_mma_kernel<<<dim3(SEQ / FBQ, BHN), 256, FA2_SMEM>>>(
        q, kh, vh, yhi, ylo);

    // 5) output projection (fp16 split-2 HMMA)
    gemm_fp16_kernel<<<dim3(NEMBD / 128, MROWS / 128), 256, GEMM_SMEM>>>(
        yhi, ylo, wp, out, MROWS, NEMBD, NEMBD);
}

// round 9
// speedup vs baseline: 2.0129x; 1.4193x over previous
#include <cuda_runtime.h>
#include <cuda_fp16.h>
#include <math.h>
#include <stdint.h>

// ---------------- problem constants ----------------
#define NEMBD   2048
#define NH      16
#define DH      128
#define BATCH   2
#define SEQ     2048
#define MROWS   (BATCH*SEQ)     // 4096
#define QKV_N   (3*NEMBD)       // 6144
#define BHN     (BATCH*NH)      // 32

// ---------------- scratch (device globals, no runtime allocs) ----------------
__device__ float g_qkv[(size_t)MROWS * QKV_N];
__device__ float g_q[(size_t)BHN*SEQ*DH];
__device__ __half g_kh[(size_t)BHN*SEQ*DH];
__device__ __half g_vh[(size_t)BHN*SEQ*DH];
__device__ __half g_xh[(size_t)MROWS*NEMBD];
__device__ __half g_wq[(size_t)QKV_N*NEMBD];
__device__ __half g_wp[(size_t)NEMBD*NEMBD];
__device__ __half g_yh[(size_t)MROWS*NEMBD];
__device__ float g_cos[SEQ*64];
__device__ float g_sin[SEQ*64];

// ================= common asm helpers =================
#define MMA16816(d, a0, a1, a2, a3, b0, b1)                                \
    asm volatile(                                                          \
        "mma.sync.aligned.m16n8k16.row.col.f32.f16.f16.f32 "               \
        "{%0,%1,%2,%3}, {%4,%5,%6,%7}, {%8,%9}, {%0,%1,%2,%3};"            \
        : "+f"((d)[0]), "+f"((d)[1]), "+f"((d)[2]), "+f"((d)[3])           \
        : "r"(a0), "r"(a1), "r"(a2), "r"(a3), "r"(b0), "r"(b1))

#define LDSM_X4(r0, r1, r2, r3, addr)                                       \
    asm volatile("ldmatrix.sync.aligned.m8n8.x4.shared.b16 "                \
                 "{%0,%1,%2,%3}, [%4];"                                     \
                 : "=r"(r0), "=r"(r1), "=r"(r2), "=r"(r3) : "r"(addr))

#define LDSM_X4T(r0, r1, r2, r3, addr)                                      \
    asm volatile("ldmatrix.sync.aligned.m8n8.x4.trans.shared.b16 "          \
                 "{%0,%1,%2,%3}, [%4];"                                     \
                 : "=r"(r0), "=r"(r1), "=r"(r2), "=r"(r3) : "r"(addr))

#define CP_ASYNC16(dst, src)                                                \
    asm volatile("cp.async.cg.shared.global [%0], [%1], 16;"                \
                 :: "r"(dst), "l"(src))
#define CP_COMMIT() asm volatile("cp.async.commit_group;" ::: "memory")
#define CP_WAIT1()  asm volatile("cp.async.wait_group 1;" ::: "memory")
#define CP_WAIT0()  asm volatile("cp.async.wait_group 0;" ::: "memory")

__device__ __forceinline__ uint32_t smem_u32(const void* p) {
    uint32_t a;
    asm("{ .reg .u64 t; cvta.to.shared.u64 t, %1; cvt.u32.u64 %0, t; }"
        : "=r"(a) : "l"(p));
    return a;
}

__device__ __forceinline__ void fp16_split2(float x, float y,
                                            uint32_t& hi, uint32_t& lo) {
    __half2 h = __floats2half2_rn(x, y);
    float rx = x - __half2float(__low2half(h));
    float ry = y - __half2float(__high2half(h));
    __half2 l = __floats2half2_rn(rx, ry);
    hi = *(uint32_t*)&h;
    lo = *(uint32_t*)&l;
}
__device__ __forceinline__ uint32_t fp16_pack2(float x, float y) {
    __half2 h = __floats2half2_rn(x, y);
    return *(uint32_t*)&h;
}

// ================= RoPE tables (fp64 angles) =================
__global__ void rope_table_kernel(float* gcos, float* gsin) {
    int idx = blockIdx.x * blockDim.x + threadIdx.x;
    if (idx >= SEQ * 64) return;
    int t = idx >> 6;
    int i = idx & 63;
    double freq = exp(-((double)(2 * i) / 128.0) * log(10000.0));
    double ang = (double)t * freq;
    gcos[idx] = (float)cos(ang);
    gsin[idx] = (float)sin(ang);
}

// ================= fp32 -> fp16 convert pass =================
__global__ void cvt_kernel(const float* __restrict__ src,
                           __half* __restrict__ dst, long long n4) {
    long long i = (long long)blockIdx.x * blockDim.x + threadIdx.x;
    if (i >= n4) return;
    float4 v = *(const float4*)(src + i * 4);
    *(uint2*)(dst + i * 4) = make_uint2(fp16_pack2(v.x, v.y), fp16_pack2(v.z, v.w));
}

// ===== plain fp16 HMMA GEMM: C[M,N] = A[M,K] * W[N,K]^T ======================
#define SLD 40
#define GARR 10240                 // bytes per array per stage (128 rows * 80B)
#define GSTG (2*GARR)              // A, W = 20480 B per stage
#define GEMM_SMEM (2*GSTG)         // 40960 B

__global__ __launch_bounds__(256, 2)
void gemm_fp16_kernel(const __half* __restrict__ A,
                      const __half* __restrict__ W,
                      float* __restrict__ C, int M, int N, int K) {
    extern __shared__ char gsm[];
    const uint32_t sb = smem_u32(gsm);

    const int tid  = threadIdx.x;
    const int warp = tid >> 5, lane = tid & 31;
    const int g = lane >> 2, t = lane & 3;
    const int wm = warp & 3, wn = warp >> 2;     // 4x2 warps; warp tile 32x64
    const int m0 = blockIdx.y * 128;
    const int n0 = blockIdx.x * 128;
    const int NT = K / 32;

    float acc[2][8][4];
#pragma unroll
    for (int mf = 0; mf < 2; mf++)
#pragma unroll
        for (int nf = 0; nf < 8; nf++)
#pragma unroll
            for (int r = 0; r < 4; r++) acc[mf][nf][r] = 0.0f;

    auto prefetch = [&](int s, int kt) {
#pragma unroll
        for (int it = 0; it < 4; it++) {
            int i = tid + it * 256;
            int arr = i >> 9;            // 0..1 : A, W
            int row = (i >> 2) & 127;
            int ch  = i & 3;
            const __half* src =
                (arr == 0) ? A + (size_t)(m0 + row) * K :
                             W + (size_t)(n0 + row) * K;
            src += kt * 32 + ch * 8;
            uint32_t dst = sb + (uint32_t)(s * GSTG + arr * GARR + row * 80 + ch * 16);
            CP_ASYNC16(dst, src);
        }
    };

    prefetch(0, 0);
    CP_COMMIT();

    for (int kt = 0; kt < NT; kt++) {
        if (kt + 1 < NT) {
            prefetch((kt + 1) & 1, kt + 1);
            CP_COMMIT();
            CP_WAIT1();
        } else {
            CP_WAIT0();
        }
        __syncthreads();

        const __half* As = (const __half*)(gsm + (size_t)(kt & 1) * GSTG);
        const __half* Ws = As + GARR / 2;

#pragma unroll
        for (int kk = 0; kk < 32; kk += 16) {
            uint32_t a[2][4];
#pragma unroll
            for (int mf = 0; mf < 2; mf++) {
                int r = wm * 32 + mf * 16 + g;
                const __half* p = &As[r * SLD + kk + 2 * t];
                a[mf][0] = *(const uint32_t*)p;
                a[mf][1] = *(const uint32_t*)(p + 8 * SLD);
                a[mf][2] = *(const uint32_t*)(p + 8);
                a[mf][3] = *(const uint32_t*)(p + 8 * SLD + 8);
            }
#pragma unroll
            for (int nf = 0; nf < 8; nf++) {
                const __half* p = &Ws[(wn * 64 + nf * 8 + g) * SLD + kk + 2 * t];
                uint32_t w0 = *(const uint32_t*)p;
                uint32_t w1 = *(const uint32_t*)(p + 8);
#pragma unroll
                for (int mf = 0; mf < 2; mf++)
                    MMA16816(acc[mf][nf], a[mf][0], a[mf][1], a[mf][2], a[mf][3], w0, w1);
            }
        }
        __syncthreads();
    }

#pragma unroll
    for (int mf = 0; mf < 2; mf++) {
        int r0 = m0 + wm * 32 + mf * 16 + g;
#pragma unroll
        for (int nf = 0; nf < 8; nf++) {
            int col = n0 + wn * 64 + nf * 8 + 2 * t;
            float* p0 = C + (size_t)r0 * N + col;
            float* p1 = C + (size_t)(r0 + 8) * N + col;
            *(float2*)p0 = make_float2(acc[mf][nf][0], acc[mf][nf][1]);
            *(float2*)p1 = make_float2(acc[mf][nf][2], acc[mf][nf][3]);
        }
    }
}

// ======== RoPE apply + transpose; emit Q fp32, K/V plain fp16 ================
__global__ void rope_apply_kernel(const float* __restrict__ qkv,
                                  const float* __restrict__ gcos,
                                  const float* __restrict__ gsin,
                                  float* __restrict__ q,
                                  __half* __restrict__ kh,
                                  __half* __restrict__ vh) {
    long long idx = (long long)blockIdx.x * blockDim.x + threadIdx.x;
    const long long total = (long long)BHN * SEQ * DH;
    if (idx >= total) return;
    int d  = (int)(idx & 127);
    int t  = (int)((idx >> 7) & (SEQ - 1));
    int bh = (int)(idx >> 18);
    int b  = bh >> 4;
    int h  = bh & 15;

    size_t base = ((size_t)(b * SEQ + t)) * QKV_N + (size_t)h * DH;
    float qv = qkv[base + d];
    float kv = qkv[base + NEMBD + d];
    float vv = qkv[base + 2 * NEMBD + d];

    int ci = d & 63;
    float c = gcos[t * 64 + ci];
    float s = gsin[t * 64 + ci];
    float qr, kr;
    if (d < 64) {
        qr = -qkv[base + d + 64];
        kr = -qkv[base + NEMBD + d + 64];
    } else {
        qr = qkv[base + d - 64];
        kr = qkv[base + NEMBD + d - 64];
    }

    size_t o = ((size_t)bh * SEQ + t) * DH + d;
    q[o] = qv * c + qr * s;
    kh[o] = __float2half_rn(kv * c + kr * s);
    vh[o] = __float2half_rn(vv);
}

// ============ flash attention on HMMA (fp16, Q/P split-2) ====================
#define FBQ 128
#define FBK 64
#define FLD 136
#define ARRB 17408u                 // 64 rows * 272 B
#define STG_B (2 * 17408)           // K, V
#define FA2_SMEM (2 * STG_B)        // 69632 B

__global__ __launch_bounds__(256, 1)
void flash_mma_kernel(const float* __restrict__ Qg,
                      const __half* __restrict__ KH,
                      const __half* __restrict__ VH,
                      __half* __restrict__ Yh) {
    extern __shared__ char smc[];
    const uint32_t sbase = smem_u32(smc);

    const int tid  = threadIdx.x;
    const int w    = tid >> 5, lane = tid & 31;
    const int g    = lane >> 2, t = lane & 3;
    const int qi   = gridDim.x - 1 - blockIdx.x;
    const int bh   = blockIdx.y;
    const int qbase = qi * FBQ;
    const int rowmax_w = qbase + w * 16 + 15;

    const size_t bhoff = (size_t)bh * SEQ * DH;

    const float scale = 0.08838834764831845f;
    uint32_t qh[8][4], ql[8][4];
    {
        const float* q0 = Qg + bhoff + (size_t)(qbase + w * 16 + g) * DH;
        const float* q1 = q0 + 8 * DH;
#pragma unroll
        for (int kf = 0; kf < 8; kf++) {
            float2 v00 = *(const float2*)(q0 + 16 * kf + 2 * t);
            float2 v10 = *(const float2*)(q1 + 16 * kf + 2 * t);
            float2 v01 = *(const float2*)(q0 + 16 * kf + 2 * t + 8);
            float2 v11 = *(const float2*)(q1 + 16 * kf + 2 * t + 8);
            fp16_split2(v00.x * scale, v00.y * scale, qh[kf][0], ql[kf][0]);
            fp16_split2(v10.x * scale, v10.y * scale, qh[kf][1], ql[kf][1]);
            fp16_split2(v01.x * scale, v01.y * scale, qh[kf][2], ql[kf][2]);
            fp16_split2(v11.x * scale, v11.y * scale, qh[kf][3], ql[kf][3]);
        }
    }

    const uint32_t lmK = (uint32_t)(((lane & 7) * FLD + (lane >> 3) * 8) * 2);
    const uint32_t lmV = (uint32_t)((((lane & 7) + ((lane >> 3) & 1) * 8) * FLD
                                     + (lane >> 4) * 8) * 2);

    float m0r = -1e30f, m1r = -1e30f, l0r = 0.0f, l1r = 0.0f;
    float o[16][4];
#pragma unroll
    for (int nf = 0; nf < 16; nf++)
#pragma unroll
        for (int r = 0; r < 4; r++) o[nf][r] = 0.0f;

    const int nkt = 2 * qi + 2;

    auto prefetch = [&](int s, int kt) {
        const int kb = kt * FBK;
        const __half* srcs[2] = { KH + bhoff + (size_t)kb * DH,
                                  VH + bhoff + (size_t)kb * DH };
        uint32_t dst0 = sbase + (uint32_t)s * STG_B;
#pragma unroll
        for (int it = 0; it < 8; it++) {
            int i = tid + it * 256;
            int arr = i >> 10, key = (i >> 4) & 63, ch = i & 15;
            const __half* src = srcs[arr] + key * DH + ch * 8;
            uint32_t dst = dst0 + (uint32_t)(arr * ARRB + key * 272 + ch * 16);
            CP_ASYNC16(dst, src);
        }
    };

    prefetch(0, 0);
    CP_COMMIT();

    for (int kt = 0; kt < nkt; kt++) {
        if (kt + 1 < nkt) {
            prefetch((kt + 1) & 1, kt + 1);
            CP_COMMIT();
            CP_WAIT1();
        } else {
            CP_WAIT0();
        }
        __syncthreads();

        const int kbase = kt * FBK;
        const bool active = (kbase <= rowmax_w);
        if (active) {
            const uint32_t stg = sbase + (uint32_t)(kt & 1) * STG_B;

            float s[8][4];
#pragma unroll
            for (int nf = 0; nf < 8; nf++)
#pragma unroll
                for (int r = 0; r < 4; r++) s[nf][r] = 0.0f;

            // ---- S = Q K^T : Qhi*K + Qlo*K ----
#pragma unroll
            for (int kf2 = 0; kf2 < 4; kf2++) {
#pragma unroll
                for (int nf = 0; nf < 8; nf++) {
                    uint32_t off = (uint32_t)((nf * 8 * FLD + kf2 * 32) * 2);
                    uint32_t k0, k1, k2, k3;
                    LDSM_X4(k0, k1, k2, k3, stg + lmK + off);
                    MMA16816(s[nf], qh[2*kf2][0], qh[2*kf2][1], qh[2*kf2][2], qh[2*kf2][3], k0, k1);
                    MMA16816(s[nf], ql[2*kf2][0], ql[2*kf2][1], ql[2*kf2][2], ql[2*kf2][3], k0, k1);
                    MMA16816(s[nf], qh[2*kf2+1][0], qh[2*kf2+1][1], qh[2*kf2+1][2], qh[2*kf2+1][3], k2, k3);
                    MMA16816(s[nf], ql[2*kf2+1][0], ql[2*kf2+1][1], ql[2*kf2+1][2], ql[2*kf2+1][3], k2, k3);
                }
            }

            const int row0 = qbase + w * 16 + g;
            const int row1 = row0 + 8;
            if (kbase + FBK - 1 > qbase + w * 16) {
#pragma unroll
                for (int nf = 0; nf < 8; nf++) {
                    int c0 = kbase + 8 * nf + 2 * t;
                    if (c0 > row0)     s[nf][0] = -1e30f;
                    if (c0 + 1 > row0) s[nf][1] = -1e30f;
                    if (c0 > row1)     s[nf][2] = -1e30f;
                    if (c0 + 1 > row1) s[nf][3] = -1e30f;
                }
            }

            float mx0 = -1e30f, mx1 = -1e30f;
#pragma unroll
            for (int nf = 0; nf < 8; nf++) {
                mx0 = fmaxf(mx0, fmaxf(s[nf][0], s[nf][1]));
                mx1 = fmaxf(mx1, fmaxf(s[nf][2], s[nf][3]));
            }
            mx0 = fmaxf(mx0, __shfl_xor_sync(0xffffffffu, mx0, 1));
            mx0 = fmaxf(mx0, __shfl_xor_sync(0xffffffffu, mx0, 2));
            mx1 = fmaxf(mx1, __shfl_xor_sync(0xffffffffu, mx1, 1));
            mx1 = fmaxf(mx1, __shfl_xor_sync(0xffffffffu, mx1, 2));
            float mn0 = fmaxf(m0r, mx0), mn1 = fmaxf(m1r, mx1);
            float a0 = __expf(m0r - mn0), a1 = __expf(m1r - mn1);
            m0r = mn0; m1r = mn1;
            float rs0 = 0.0f, rs1 = 0.0f;
#pragma unroll
            for (int nf = 0; nf < 8; nf++) {
                s[nf][0] = __expf(s[nf][0] - mn0);
                s[nf][1] = __expf(s[nf][1] - mn0);
                s[nf][2] = __expf(s[nf][2] - mn1);
                s[nf][3] = __expf(s[nf][3] - mn1);
                rs0 += s[nf][0] + s[nf][1];
                rs1 += s[nf][2] + s[nf][3];
            }
            rs0 += __shfl_xor_sync(0xffffffffu, rs0, 1);
            rs0 += __shfl_xor_sync(0xffffffffu, rs0, 2);
            rs1 += __shfl_xor_sync(0xffffffffu, rs1, 1);
            rs1 += __shfl_xor_sync(0xffffffffu, rs1, 2);
            l0r = l0r * a0 + rs0;
            l1r = l1r * a1 + rs1;
#pragma unroll
            for (int nf = 0; nf < 16; nf++) {
                o[nf][0] *= a0; o[nf][1] *= a0;
                o[nf][2] *= a1; o[nf][3] *= a1;
            }

            // ---- O += P V : Phi*V + Plo*V ----
#pragma unroll
            for (int kf = 0; kf < 4; kf++) {
                uint32_t ph[4], pl[4];
                fp16_split2(s[2*kf][0],   s[2*kf][1],   ph[0], pl[0]);
                fp16_split2(s[2*kf][2],   s[2*kf][3],   ph[1], pl[1]);
                fp16_split2(s[2*kf+1][0], s[2*kf+1][1], ph[2], pl[2]);
                fp16_split2(s[2*kf+1][2], s[2*kf+1][3], ph[3], pl[3]);
                uint32_t voff = (uint32_t)((kf * 16 * FLD) * 2);
#pragma unroll
                for (int nf2 = 0; nf2 < 8; nf2++) {
                    uint32_t off = voff + (uint32_t)(nf2 * 32);
                    uint32_t v0, v1, v2, v3;
                    LDSM_X4T(v0, v1, v2, v3, stg + ARRB + lmV + off);
                    MMA16816(o[2*nf2],   ph[0], ph[1], ph[2], ph[3], v0, v1);
                    MMA16816(o[2*nf2],   pl[0], pl[1], pl[2], pl[3], v0, v1);
                    MMA16816(o[2*nf2+1], ph[0], ph[1], ph[2], ph[3], v2, v3);
                    MMA16816(o[2*nf2+1], pl[0], pl[1], pl[2], pl[3], v2, v3);
                }
            }
        }
        __syncthreads();
    }

    // ---- epilogue: write y as plain fp16 ----
    const int b = bh >> 4, h = bh & 15;
    const int row0 = qbase + w * 16 + g;
    const float inv0 = 1.0f / l0r, inv1 = 1.0f / l1r;
    size_t y0off = ((size_t)(b * SEQ + row0)) * NEMBD + h * DH;
    size_t y1off = ((size_t)(b * SEQ + row0 + 8)) * NEMBD + h * DH;
#pragma unroll
    for (int nf = 0; nf < 16; nf++) {
        int col = 8 * nf + 2 * t;
        *(uint32_t*)(Yh + y0off + col) = fp16_pack2(o[nf][0] * inv0, o[nf][1] * inv0);
        *(uint32_t*)(Yh + y1off + col) = fp16_pack2(o[nf][2] * inv1, o[nf][3] * inv1);
    }
}

// ================= launch =====================================================
extern "C" void kernel_launch(void* const* d_in, const int* in_sizes, int n_in,
                              void* d_out, int out_size) {
    const float* x      = (const float*)d_in[0];
    const float* w_qkv  = (const float*)d_in[1];
    const float* w_proj = (const float*)d_in[2];
    float* out = (float*)d_out;

    float *qkv, *q, *gc, *gs;
    __half *kh, *vh, *xh, *wq, *wp, *yh;
    cudaGetSymbolAddress((void**)&qkv, g_qkv);
    cudaGetSymbolAddress((void**)&q, g_q);
    cudaGetSymbolAddress((void**)&kh, g_kh);
    cudaGetSymbolAddress((void**)&vh, g_vh);
    cudaGetSymbolAddress((void**)&xh, g_xh);
    cudaGetSymbolAddress((void**)&wq, g_wq);
    cudaGetSymbolAddress((void**)&wp, g_wp);
    cudaGetSymbolAddress((void**)&yh, g_yh);
    cudaGetSymbolAddress((void**)&gc, g_cos);
    cudaGetSymbolAddress((void**)&gs, g_sin);

    // 1) RoPE tables + operand conversions
    rope_table_kernel<<<(SEQ * 64 + 255) / 256, 256>>>(gc, gs);
    {
        long long n4;
        n4 = (long long)MROWS * NEMBD / 4;
        cvt_kernel<<<(unsigned)((n4 + 255) / 256), 256>>>(x, xh, n4);
        n4 = (long long)QKV_N * NEMBD / 4;
        cvt_kernel<<<(unsigned)((n4 + 255) / 256), 256>>>(w_qkv, wq, n4);
        n4 = (long long)NEMBD * NEMBD / 4;
        cvt_kernel<<<(unsigned)((n4 + 255) / 256), 256>>>(w_proj, wp, n4);
    }

    // 2) QKV projection (plain fp16 HMMA)
    cudaFuncSetAttribute(gemm_fp16_kernel,
                         cudaFuncAttributeMaxDynamicSharedMemorySize, GEMM_SMEM);
    gemm_fp16_kernel<<<dim3(QKV_N / 128, MROWS / 128), 256, GEMM_SMEM>>>(
        xh, wq, qkv, MROWS, QKV_N, NEMBD);

    // 3) RoPE + transpose + K/V fp16 convert
    {
        long long total = (long long)BHN * SEQ * DH;
        rope_apply_kernel<<<(unsigned)((total + 255) / 256), 256>>>(
            qkv, gc, gs, q, kh, vh);
    }

    // 4) flash attention (fp16 HMMA, Q/P split-2) -> y fp16
    cudaFuncSetAttribute(flash_mma_kernel,
                         cudaFuncAttributeMaxDynamicSharedMemorySize, FA2_SMEM);
    flash_mma_kernel<<<dim3(SEQ / FBQ, BHN), 256, FA2_SMEM>>>(
        q, kh, vh, yh);

    // 5) output projection (plain fp16 HMMA)
    gemm_fp16_kernel<<<dim3(NEMBD / 128, MROWS / 128), 256, GEMM_SMEM>>>(
        yh, wp, out, MROWS, NEMBD, NEMBD);
}

// round 10
// speedup vs baseline: 2.2224x; 1.1041x over previous
#include <cuda_runtime.h>
#include <cuda_fp16.h>
#include <math.h>
#include <stdint.h>

// ---------------- problem constants ----------------
#define NEMBD   2048
#define NH      16
#define DH      128
#define BATCH   2
#define SEQ     2048
#define MROWS   (BATCH*SEQ)     // 4096
#define QKV_N   (3*NEMBD)       // 6144
#define BHN     (BATCH*NH)      // 32

// ---------------- scratch (device globals, no runtime allocs) ----------------
__device__ float g_qkv[(size_t)MROWS * QKV_N];
__device__ __half g_qh[(size_t)BHN*SEQ*DH];
__device__ __half g_kh[(size_t)BHN*SEQ*DH];
__device__ __half g_vh[(size_t)BHN*SEQ*DH];
__device__ __half g_xh[(size_t)MROWS*NEMBD];
__device__ __half g_wq[(size_t)QKV_N*NEMBD];
__device__ __half g_wp[(size_t)NEMBD*NEMBD];
__device__ __half g_yh[(size_t)MROWS*NEMBD];
__device__ float g_cos[SEQ*64];
__device__ float g_sin[SEQ*64];

// ================= common asm helpers =================
#define MMA16816(d, a0, a1, a2, a3, b0, b1)                                \
    asm volatile(                                                          \
        "mma.sync.aligned.m16n8k16.row.col.f32.f16.f16.f32 "               \
        "{%0,%1,%2,%3}, {%4,%5,%6,%7}, {%8,%9}, {%0,%1,%2,%3};"            \
        : "+f"((d)[0]), "+f"((d)[1]), "+f"((d)[2]), "+f"((d)[3])           \
        : "r"(a0), "r"(a1), "r"(a2), "r"(a3), "r"(b0), "r"(b1))

#define LDSM_X4(r0, r1, r2, r3, addr)                                       \
    asm volatile("ldmatrix.sync.aligned.m8n8.x4.shared.b16 "                \
                 "{%0,%1,%2,%3}, [%4];"                                     \
                 : "=r"(r0), "=r"(r1), "=r"(r2), "=r"(r3) : "r"(addr))

#define LDSM_X4T(r0, r1, r2, r3, addr)                                      \
    asm volatile("ldmatrix.sync.aligned.m8n8.x4.trans.shared.b16 "          \
                 "{%0,%1,%2,%3}, [%4];"                                     \
                 : "=r"(r0), "=r"(r1), "=r"(r2), "=r"(r3) : "r"(addr))

#define CP_ASYNC16(dst, src)                                                \
    asm volatile("cp.async.cg.shared.global [%0], [%1], 16;"                \
                 :: "r"(dst), "l"(src))
#define CP_COMMIT() asm volatile("cp.async.commit_group;" ::: "memory")
#define CP_WAIT1()  asm volatile("cp.async.wait_group 1;" ::: "memory")
#define CP_WAIT0()  asm volatile("cp.async.wait_group 0;" ::: "memory")

__device__ __forceinline__ uint32_t smem_u32(const void* p) {
    uint32_t a;
    asm("{ .reg .u64 t; cvta.to.shared.u64 t, %1; cvt.u32.u64 %0, t; }"
        : "=r"(a) : "l"(p));
    return a;
}

__device__ __forceinline__ uint32_t fp16_pack2(float x, float y) {
    __half2 h = __floats2half2_rn(x, y);
    return *(uint32_t*)&h;
}

// ================= RoPE tables (fp64 angles) =================
__global__ void rope_table_kernel(float* gcos, float* gsin) {
    int idx = blockIdx.x * blockDim.x + threadIdx.x;
    if (idx >= SEQ * 64) return;
    int t = idx >> 6;
    int i = idx & 63;
    double freq = exp(-((double)(2 * i) / 128.0) * log(10000.0));
    double ang = (double)t * freq;
    gcos[idx] = (float)cos(ang);
    gsin[idx] = (float)sin(ang);
}

// ================= fp32 -> fp16 convert pass =================
__global__ void cvt_kernel(const float* __restrict__ src,
                           __half* __restrict__ dst, long long n4) {
    long long i = (long long)blockIdx.x * blockDim.x + threadIdx.x;
    if (i >= n4) return;
    float4 v = *(const float4*)(src + i * 4);
    *(uint2*)(dst + i * 4) = make_uint2(fp16_pack2(v.x, v.y), fp16_pack2(v.z, v.w));
}

// ===== plain fp16 HMMA GEMM: C[M,N] = A[M,K] * W[N,K]^T ======================
#define SLD 40
#define GARR 10240                 // bytes per array per stage (128 rows * 80B)
#define GSTG (2*GARR)              // A, W = 20480 B per stage
#define GEMM_SMEM (2*GSTG)         // 40960 B

__global__ __launch_bounds__(256, 2)
void gemm_fp16_kernel(const __half* __restrict__ A,
                      const __half* __restrict__ W,
                      float* __restrict__ C, int M, int N, int K) {
    extern __shared__ char gsm[];
    const uint32_t sb = smem_u32(gsm);

    const int tid  = threadIdx.x;
    const int warp = tid >> 5, lane = tid & 31;
    const int g = lane >> 2, t = lane & 3;
    const int wm = warp & 3, wn = warp >> 2;     // 4x2 warps; warp tile 32x64
    const int m0 = blockIdx.y * 128;
    const int n0 = blockIdx.x * 128;
    const int NT = K / 32;

    float acc[2][8][4];
#pragma unroll
    for (int mf = 0; mf < 2; mf++)
#pragma unroll
        for (int nf = 0; nf < 8; nf++)
#pragma unroll
            for (int r = 0; r < 4; r++) acc[mf][nf][r] = 0.0f;

    auto prefetch = [&](int s, int kt) {
#pragma unroll
        for (int it = 0; it < 4; it++) {
            int i = tid + it * 256;
            int arr = i >> 9;            // 0..1 : A, W
            int row = (i >> 2) & 127;
            int ch  = i & 3;
            const __half* src =
                (arr == 0) ? A + (size_t)(m0 + row) * K :
                             W + (size_t)(n0 + row) * K;
            src += kt * 32 + ch * 8;
            uint32_t dst = sb + (uint32_t)(s * GSTG + arr * GARR + row * 80 + ch * 16);
            CP_ASYNC16(dst, src);
        }
    };

    prefetch(0, 0);
    CP_COMMIT();

    for (int kt = 0; kt < NT; kt++) {
        if (kt + 1 < NT) {
            prefetch((kt + 1) & 1, kt + 1);
            CP_COMMIT();
            CP_WAIT1();
        } else {
            CP_WAIT0();
        }
        __syncthreads();

        const __half* As = (const __half*)(gsm + (size_t)(kt & 1) * GSTG);
        const __half* Ws = As + GARR / 2;

#pragma unroll
        for (int kk = 0; kk < 32; kk += 16) {
            uint32_t a[2][4];
#pragma unroll
            for (int mf = 0; mf < 2; mf++) {
                int r = wm * 32 + mf * 16 + g;
                const __half* p = &As[r * SLD + kk + 2 * t];
                a[mf][0] = *(const uint32_t*)p;
                a[mf][1] = *(const uint32_t*)(p + 8 * SLD);
                a[mf][2] = *(const uint32_t*)(p + 8);
                a[mf][3] = *(const uint32_t*)(p + 8 * SLD + 8);
            }
#pragma unroll
            for (int nf = 0; nf < 8; nf++) {
                const __half* p = &Ws[(wn * 64 + nf * 8 + g) * SLD + kk + 2 * t];
                uint32_t w0 = *(const uint32_t*)p;
                uint32_t w1 = *(const uint32_t*)(p + 8);
#pragma unroll
                for (int mf = 0; mf < 2; mf++)
                    MMA16816(acc[mf][nf], a[mf][0], a[mf][1], a[mf][2], a[mf][3], w0, w1);
            }
        }
        __syncthreads();
    }

#pragma unroll
    for (int mf = 0; mf < 2; mf++) {
        int r0 = m0 + wm * 32 + mf * 16 + g;
#pragma unroll
        for (int nf = 0; nf < 8; nf++) {
            int col = n0 + wn * 64 + nf * 8 + 2 * t;
            float* p0 = C + (size_t)r0 * N + col;
            float* p1 = C + (size_t)(r0 + 8) * N + col;
            *(float2*)p0 = make_float2(acc[mf][nf][0], acc[mf][nf][1]);
            *(float2*)p1 = make_float2(acc[mf][nf][2], acc[mf][nf][3]);
        }
    }
}

// === RoPE apply + transpose; emit Q (scaled) / K / V as plain fp16 ===========
__global__ void rope_apply_kernel(const float* __restrict__ qkv,
                                  const float* __restrict__ gcos,
                                  const float* __restrict__ gsin,
                                  __half* __restrict__ qh,
                                  __half* __restrict__ kh,
                                  __half* __restrict__ vh) {
    long long idx = (long long)blockIdx.x * blockDim.x + threadIdx.x;
    const long long total = (long long)BHN * SEQ * DH;
    if (idx >= total) return;
    int d  = (int)(idx & 127);
    int t  = (int)((idx >> 7) & (SEQ - 1));
    int bh = (int)(idx >> 18);
    int b  = bh >> 4;
    int h  = bh & 15;

    size_t base = ((size_t)(b * SEQ + t)) * QKV_N + (size_t)h * DH;
    float qv = qkv[base + d];
    float kv = qkv[base + NEMBD + d];
    float vv = qkv[base + 2 * NEMBD + d];

    int ci = d & 63;
    float c = gcos[t * 64 + ci];
    float s = gsin[t * 64 + ci];
    float qr, kr;
    if (d < 64) {
        qr = -qkv[base + d + 64];
        kr = -qkv[base + NEMBD + d + 64];
    } else {
        qr = qkv[base + d - 64];
        kr = qkv[base + NEMBD + d - 64];
    }

    const float scale = 0.08838834764831845f;   // 1/sqrt(128) folded into Q
    size_t o = ((size_t)bh * SEQ + t) * DH + d;
    qh[o] = __float2half_rn((qv * c + qr * s) * scale);
    kh[o] = __float2half_rn(kv * c + kr * s);
    vh[o] = __float2half_rn(vv);
}

// ============ flash attention on HMMA (all plain fp16) =======================
#define FBQ 128
#define FBK 64
#define FLD 136
#define ARRB 17408u                 // 64 rows * 272 B
#define STG_B (2 * 17408)           // K, V
#define FA2_SMEM (2 * STG_B)        // 69632 B

__global__ __launch_bounds__(256, 1)
void flash_mma_kernel(const __half* __restrict__ Qg,
                      const __half* __restrict__ KH,
                      const __half* __restrict__ VH,
                      __half* __restrict__ Yh) {
    extern __shared__ char smc[];
    const uint32_t sbase = smem_u32(smc);

    const int tid  = threadIdx.x;
    const int w    = tid >> 5, lane = tid & 31;
    const int g    = lane >> 2, t = lane & 3;
    const int qi   = gridDim.x - 1 - blockIdx.x;
    const int bh   = blockIdx.y;
    const int qbase = qi * FBQ;
    const int rowmax_w = qbase + w * 16 + 15;

    const size_t bhoff = (size_t)bh * SEQ * DH;

    // ---- load Q fragments (pre-scaled fp16 in gmem) ----
    uint32_t qf[8][4];
    {
        const __half* q0 = Qg + bhoff + (size_t)(qbase + w * 16 + g) * DH;
        const __half* q1 = q0 + 8 * DH;
#pragma unroll
        for (int kf = 0; kf < 8; kf++) {
            qf[kf][0] = *(const uint32_t*)(q0 + 16 * kf + 2 * t);
            qf[kf][1] = *(const uint32_t*)(q1 + 16 * kf + 2 * t);
            qf[kf][2] = *(const uint32_t*)(q0 + 16 * kf + 2 * t + 8);
            qf[kf][3] = *(const uint32_t*)(q1 + 16 * kf + 2 * t + 8);
        }
    }

    const uint32_t lmK = (uint32_t)(((lane & 7) * FLD + (lane >> 3) * 8) * 2);
    const uint32_t lmV = (uint32_t)((((lane & 7) + ((lane >> 3) & 1) * 8) * FLD
                                     + (lane >> 4) * 8) * 2);

    float m0r = -1e30f, m1r = -1e30f, l0r = 0.0f, l1r = 0.0f;
    float o[16][4];
#pragma unroll
    for (int nf = 0; nf < 16; nf++)
#pragma unroll
        for (int r = 0; r < 4; r++) o[nf][r] = 0.0f;

    const int nkt = 2 * qi + 2;

    auto prefetch = [&](int s, int kt) {
        const int kb = kt * FBK;
        const __half* srcs[2] = { KH + bhoff + (size_t)kb * DH,
                                  VH + bhoff + (size_t)kb * DH };
        uint32_t dst0 = sbase + (uint32_t)s * STG_B;
#pragma unroll
        for (int it = 0; it < 8; it++) {
            int i = tid + it * 256;
            int arr = i >> 10, key = (i >> 4) & 63, ch = i & 15;
            const __half* src = srcs[arr] + key * DH + ch * 8;
            uint32_t dst = dst0 + (uint32_t)(arr * ARRB + key * 272 + ch * 16);
            CP_ASYNC16(dst, src);
        }
    };

    prefetch(0, 0);
    CP_COMMIT();

    for (int kt = 0; kt < nkt; kt++) {
        if (kt + 1 < nkt) {
            prefetch((kt + 1) & 1, kt + 1);
            CP_COMMIT();
            CP_WAIT1();
        } else {
            CP_WAIT0();
        }
        __syncthreads();

        const int kbase = kt * FBK;
        const bool active = (kbase <= rowmax_w);
        if (active) {
            const uint32_t stg = sbase + (uint32_t)(kt & 1) * STG_B;

            float s[8][4];
#pragma unroll
            for (int nf = 0; nf < 8; nf++)
#pragma unroll
                for (int r = 0; r < 4; r++) s[nf][r] = 0.0f;

            // ---- S = Q K^T (plain fp16) ----
#pragma unroll
            for (int kf2 = 0; kf2 < 4; kf2++) {
#pragma unroll
                for (int nf = 0; nf < 8; nf++) {
                    uint32_t off = (uint32_t)((nf * 8 * FLD + kf2 * 32) * 2);
                    uint32_t k0, k1, k2, k3;
                    LDSM_X4(k0, k1, k2, k3, stg + lmK + off);
                    MMA16816(s[nf], qf[2*kf2][0], qf[2*kf2][1], qf[2*kf2][2], qf[2*kf2][3], k0, k1);
                    MMA16816(s[nf], qf[2*kf2+1][0], qf[2*kf2+1][1], qf[2*kf2+1][2], qf[2*kf2+1][3], k2, k3);
                }
            }

            const int row0 = qbase + w * 16 + g;
            const int row1 = row0 + 8;
            if (kbase + FBK - 1 > qbase + w * 16) {
#pragma unroll
                for (int nf = 0; nf < 8; nf++) {
                    int c0 = kbase + 8 * nf + 2 * t;
                    if (c0 > row0)     s[nf][0] = -1e30f;
                    if (c0 + 1 > row0) s[nf][1] = -1e30f;
                    if (c0 > row1)     s[nf][2] = -1e30f;
                    if (c0 + 1 > row1) s[nf][3] = -1e30f;
                }
            }

            float mx0 = -1e30f, mx1 = -1e30f;
#pragma unroll
            for (int nf = 0; nf < 8; nf++) {
                mx0 = fmaxf(mx0, fmaxf(s[nf][0], s[nf][1]));
                mx1 = fmaxf(mx1, fmaxf(s[nf][2], s[nf][3]));
            }
            mx0 = fmaxf(mx0, __shfl_xor_sync(0xffffffffu, mx0, 1));
            mx0 = fmaxf(mx0, __shfl_xor_sync(0xffffffffu, mx0, 2));
            mx1 = fmaxf(mx1, __shfl_xor_sync(0xffffffffu, mx1, 1));
            mx1 = fmaxf(mx1, __shfl_xor_sync(0xffffffffu, mx1, 2));
            float mn0 = fmaxf(m0r, mx0), mn1 = fmaxf(m1r, mx1);
            float a0 = __expf(m0r - mn0), a1 = __expf(m1r - mn1);
            m0r = mn0; m1r = mn1;
            float rs0 = 0.0f, rs1 = 0.0f;
#pragma unroll
            for (int nf = 0; nf < 8; nf++) {
                s[nf][0] = __expf(s[nf][0] - mn0);
                s[nf][1] = __expf(s[nf][1] - mn0);
                s[nf][2] = __expf(s[nf][2] - mn1);
                s[nf][3] = __expf(s[nf][3] - mn1);
                rs0 += s[nf][0] + s[nf][1];
                rs1 += s[nf][2] + s[nf][3];
            }
            rs0 += __shfl_xor_sync(0xffffffffu, rs0, 1);
            rs0 += __shfl_xor_sync(0xffffffffu, rs0, 2);
            rs1 += __shfl_xor_sync(0xffffffffu, rs1, 1);
            rs1 += __shfl_xor_sync(0xffffffffu, rs1, 2);
            l0r = l0r * a0 + rs0;
            l1r = l1r * a1 + rs1;
#pragma unroll
            for (int nf = 0; nf < 16; nf++) {
                o[nf][0] *= a0; o[nf][1] *= a0;
                o[nf][2] *= a1; o[nf][3] *= a1;
            }

            // ---- O += P V (plain fp16 P) ----
#pragma unroll
            for (int kf = 0; kf < 4; kf++) {
                uint32_t ph[4];
                ph[0] = fp16_pack2(s[2*kf][0],   s[2*kf][1]);
                ph[1] = fp16_pack2(s[2*kf][2],   s[2*kf][3]);
                ph[2] = fp16_pack2(s[2*kf+1][0], s[2*kf+1][1]);
                ph[3] = fp16_pack2(s[2*kf+1][2], s[2*kf+1][3]);
                uint32_t voff = (uint32_t)((kf * 16 * FLD) * 2);
#pragma unroll
                for (int nf2 = 0; nf2 < 8; nf2++) {
                    uint32_t off = voff + (uint32_t)(nf2 * 32);
                    uint32_t v0, v1, v2, v3;
                    LDSM_X4T(v0, v1, v2, v3, stg + ARRB + lmV + off);
                    MMA16816(o[2*nf2],   ph[0], ph[1], ph[2], ph[3], v0, v1);
                    MMA16816(o[2*nf2+1], ph[0], ph[1], ph[2], ph[3], v2, v3);
                }
            }
        }
        __syncthreads();
    }

    // ---- epilogue: write y as plain fp16 ----
    const int b = bh >> 4, h = bh & 15;
    const int row0 = qbase + w * 16 + g;
    const float inv0 = 1.0f / l0r, inv1 = 1.0f / l1r;
    size_t y0off = ((size_t)(b * SEQ + row0)) * NEMBD + h * DH;
    size_t y1off = ((size_t)(b * SEQ + row0 + 8)) * NEMBD + h * DH;
#pragma unroll
    for (int nf = 0; nf < 16; nf++) {
        int col = 8 * nf + 2 * t;
        *(uint32_t*)(Yh + y0off + col) = fp16_pack2(o[nf][0] * inv0, o[nf][1] * inv0);
        *(uint32_t*)(Yh + y1off + col) = fp16_pack2(o[nf][2] * inv1, o[nf][3] * inv1);
    }
}

// ================= launch =====================================================
extern "C" void kernel_launch(void* const* d_in, const int* in_sizes, int n_in,
                              void* d_out, int out_size) {
    const float* x      = (const float*)d_in[0];
    const float* w_qkv  = (const float*)d_in[1];
    const float* w_proj = (const float*)d_in[2];
    float* out = (float*)d_out;

    float *qkv, *gc, *gs;
    __half *qh, *kh, *vh, *xh, *wq, *wp, *yh;
    cudaGetSymbolAddress((void**)&qkv, g_qkv);
    cudaGetSymbolAddress((void**)&qh, g_qh);
    cudaGetSymbolAddress((void**)&kh, g_kh);
    cudaGetSymbolAddress((void**)&vh, g_vh);
    cudaGetSymbolAddress((void**)&xh, g_xh);
    cudaGetSymbolAddress((void**)&wq, g_wq);
    cudaGetSymbolAddress((void**)&wp, g_wp);
    cudaGetSymbolAddress((void**)&yh, g_yh);
    cudaGetSymbolAddress((void**)&gc, g_cos);
    cudaGetSymbolAddress((void**)&gs, g_sin);

    // 1) RoPE tables + operand conversions
    rope_table_kernel<<<(SEQ * 64 + 255) / 256, 256>>>(gc, gs);
    {
        long long n4;
        n4 = (long long)MROWS * NEMBD / 4;
        cvt_kernel<<<(unsigned)((n4 + 255) / 256), 256>>>(x, xh, n4);
        n4 = (long long)QKV_N * NEMBD / 4;
        cvt_kernel<<<(unsigned)((n4 + 255) / 256), 256>>>(w_qkv, wq, n4);
        n4 = (long long)NEMBD * NEMBD / 4;
        cvt_kernel<<<(unsigned)((n4 + 255) / 256), 256>>>(w_proj, wp, n4);
    }

    // 2) QKV projection (plain fp16 HMMA)
    cudaFuncSetAttribute(gemm_fp16_kernel,
                         cudaFuncAttributeMaxDynamicSharedMemorySize, GEMM_SMEM);
    gemm_fp16_kernel<<<dim3(QKV_N / 128, MROWS / 128), 256, GEMM_SMEM>>>(
        xh, wq, qkv, MROWS, QKV_N, NEMBD);

    // 3) RoPE + transpose -> Q(scaled)/K/V fp16
    {
        long long total = (long long)BHN * SEQ * DH;
        rope_apply_kernel<<<(unsigned)((total + 255) / 256), 256>>>(
            qkv, gc, gs, qh, kh, vh);
    }

    // 4) flash attention (plain fp16 HMMA) -> y fp16
    cudaFuncSetAttribute(flash_mma_kernel,
                         cudaFuncAttributeMaxDynamicSharedMemorySize, FA2_SMEM);
    flash_mma_kernel<<<dim3(SEQ / FBQ, BHN), 256, FA2_SMEM>>>(
        qh, kh, vh, yh);

    // 5) output projection (plain fp16 HMMA)
    gemm_fp16_kernel<<<dim3(NEMBD / 128, MROWS / 128), 256, GEMM_SMEM>>>(
        yh, wp, out, MROWS, NEMBD, NEMBD);
}

// round 11
// speedup vs baseline: 2.3414x; 1.0535x over previous
#include <cuda_runtime.h>
#include <cuda_fp16.h>
#include <math.h>
#include <stdint.h>

// ---------------- problem constants ----------------
#define NEMBD   2048
#define NH      16
#define DH      128
#define BATCH   2
#define SEQ     2048
#define MROWS   (BATCH*SEQ)     // 4096
#define QKV_N   (3*NEMBD)       // 6144
#define BHN     (BATCH*NH)      // 32

// ---------------- scratch (device globals, no runtime allocs) ----------------
__device__ __half g_qh[(size_t)BHN*SEQ*DH];
__device__ __half g_kh[(size_t)BHN*SEQ*DH];
__device__ __half g_vh[(size_t)BHN*SEQ*DH];
__device__ __half g_xh[(size_t)MROWS*NEMBD];
__device__ __half g_wq[(size_t)QKV_N*NEMBD];
__device__ __half g_wp[(size_t)NEMBD*NEMBD];
__device__ __half g_yh[(size_t)MROWS*NEMBD];
__device__ float g_cos[SEQ*64];
__device__ float g_sin[SEQ*64];

// ================= common asm helpers =================
#define MMA16816(d, a0, a1, a2, a3, b0, b1)                                \
    asm volatile(                                                          \
        "mma.sync.aligned.m16n8k16.row.col.f32.f16.f16.f32 "               \
        "{%0,%1,%2,%3}, {%4,%5,%6,%7}, {%8,%9}, {%0,%1,%2,%3};"            \
        : "+f"((d)[0]), "+f"((d)[1]), "+f"((d)[2]), "+f"((d)[3])           \
        : "r"(a0), "r"(a1), "r"(a2), "r"(a3), "r"(b0), "r"(b1))

#define LDSM_X4(r0, r1, r2, r3, addr)                                       \
    asm volatile("ldmatrix.sync.aligned.m8n8.x4.shared.b16 "                \
                 "{%0,%1,%2,%3}, [%4];"                                     \
                 : "=r"(r0), "=r"(r1), "=r"(r2), "=r"(r3) : "r"(addr))

#define LDSM_X4T(r0, r1, r2, r3, addr)                                      \
    asm volatile("ldmatrix.sync.aligned.m8n8.x4.trans.shared.b16 "          \
                 "{%0,%1,%2,%3}, [%4];"                                     \
                 : "=r"(r0), "=r"(r1), "=r"(r2), "=r"(r3) : "r"(addr))

#define CP_ASYNC16(dst, src)                                                \
    asm volatile("cp.async.cg.shared.global [%0], [%1], 16;"                \
                 :: "r"(dst), "l"(src))
#define CP_COMMIT() asm volatile("cp.async.commit_group;" ::: "memory")
#define CP_WAIT1()  asm volatile("cp.async.wait_group 1;" ::: "memory")
#define CP_WAIT0()  asm volatile("cp.async.wait_group 0;" ::: "memory")

__device__ __forceinline__ uint32_t smem_u32(const void* p) {
    uint32_t a;
    asm("{ .reg .u64 t; cvta.to.shared.u64 t, %1; cvt.u32.u64 %0, t; }"
        : "=r"(a) : "l"(p));
    return a;
}

__device__ __forceinline__ uint32_t fp16_pack2(float x, float y) {
    __half2 h = __floats2half2_rn(x, y);
    return *(uint32_t*)&h;
}

// ================= RoPE tables (fp64 angles) =================
__global__ void rope_table_kernel(float* gcos, float* gsin) {
    int idx = blockIdx.x * blockDim.x + threadIdx.x;
    if (idx >= SEQ * 64) return;
    int t = idx >> 6;
    int i = idx & 63;
    double freq = exp(-((double)(2 * i) / 128.0) * log(10000.0));
    double ang = (double)t * freq;
    gcos[idx] = (float)cos(ang);
    gsin[idx] = (float)sin(ang);
}

// ================= fp32 -> fp16 convert pass =================
__global__ void cvt_kernel(const float* __restrict__ src,
                           __half* __restrict__ dst, long long n4) {
    long long i = (long long)blockIdx.x * blockDim.x + threadIdx.x;
    if (i >= n4) return;
    float4 v = *(const float4*)(src + i * 4);
    *(uint2*)(dst + i * 4) = make_uint2(fp16_pack2(v.x, v.y), fp16_pack2(v.z, v.w));
}

// ================= shared GEMM tiling constants =================
#define SLD 40
#define GARR 10240                 // bytes per array per stage (128 rows * 80B)
#define GSTG (2*GARR)              // A, W = 20480 B per stage
#define GEMM_SMEM (2*GSTG)         // 40960 B  (also holds 64x132 fp32 stage = 33792 B)
#define RLD 132                    // epilogue stage row stride (floats)

// ===== QKV GEMM with fused RoPE epilogue =====================================
// C-tile (128x128) covers exactly one (part, head): part = n0>>11, h = (n0&2047)>>7.
__global__ __launch_bounds__(256, 2)
void gemm_qkv_rope_kernel(const __half* __restrict__ A,
                          const __half* __restrict__ W,
                          const float* __restrict__ gcos,
                          const float* __restrict__ gsin,
                          __half* __restrict__ qh,
                          __half* __restrict__ kh,
                          __half* __restrict__ vh) {
    extern __shared__ char gsm[];
    const uint32_t sb = smem_u32(gsm);
    const int K = NEMBD;

    const int tid  = threadIdx.x;
    const int warp = tid >> 5, lane = tid & 31;
    const int g = lane >> 2, t = lane & 3;
    const int wm = warp & 3, wn = warp >> 2;
    const int m0 = blockIdx.y * 128;
    const int n0 = blockIdx.x * 128;
    const int NT = K / 32;

    float acc[2][8][4];
#pragma unroll
    for (int mf = 0; mf < 2; mf++)
#pragma unroll
        for (int nf = 0; nf < 8; nf++)
#pragma unroll
            for (int r = 0; r < 4; r++) acc[mf][nf][r] = 0.0f;

    auto prefetch = [&](int s, int kt) {
#pragma unroll
        for (int it = 0; it < 4; it++) {
            int i = tid + it * 256;
            int arr = i >> 9;
            int row = (i >> 2) & 127;
            int ch  = i & 3;
            const __half* src =
                (arr == 0) ? A + (size_t)(m0 + row) * K :
                             W + (size_t)(n0 + row) * K;
            src += kt * 32 + ch * 8;
            uint32_t dst = sb + (uint32_t)(s * GSTG + arr * GARR + row * 80 + ch * 16);
            CP_ASYNC16(dst, src);
        }
    };

    prefetch(0, 0);
    CP_COMMIT();

    for (int kt = 0; kt < NT; kt++) {
        if (kt + 1 < NT) {
            prefetch((kt + 1) & 1, kt + 1);
            CP_COMMIT();
            CP_WAIT1();
        } else {
            CP_WAIT0();
        }
        __syncthreads();

        const __half* As = (const __half*)(gsm + (size_t)(kt & 1) * GSTG);
        const __half* Ws = As + GARR / 2;

#pragma unroll
        for (int kk = 0; kk < 32; kk += 16) {
            uint32_t a[2][4];
#pragma unroll
            for (int mf = 0; mf < 2; mf++) {
                int r = wm * 32 + mf * 16 + g;
                const __half* p = &As[r * SLD + kk + 2 * t];
                a[mf][0] = *(const uint32_t*)p;
                a[mf][1] = *(const uint32_t*)(p + 8 * SLD);
                a[mf][2] = *(const uint32_t*)(p + 8);
                a[mf][3] = *(const uint32_t*)(p + 8 * SLD + 8);
            }
#pragma unroll
            for (int nf = 0; nf < 8; nf++) {
                const __half* p = &Ws[(wn * 64 + nf * 8 + g) * SLD + kk + 2 * t];
                uint32_t w0 = *(const uint32_t*)p;
                uint32_t w1 = *(const uint32_t*)(p + 8);
#pragma unroll
                for (int mf = 0; mf < 2; mf++)
                    MMA16816(acc[mf][nf], a[mf][0], a[mf][1], a[mf][2], a[mf][3], w0, w1);
            }
        }
        __syncthreads();
    }

    // ---------------- fused epilogue ----------------
    const int part = n0 >> 11;          // 0=q, 1=k, 2=v
    const int h    = (n0 & 2047) >> 7;

    if (part == 2) {
        // V: no RoPE, direct fp16 write in [bh, t, d]
#pragma unroll
        for (int mf = 0; mf < 2; mf++) {
            int m = m0 + wm * 32 + mf * 16 + g;
            int b0 = m >> 11, t0 = m & 2047;
            int b1 = (m + 8) >> 11, t1 = (m + 8) & 2047;
            size_t o0 = ((size_t)(b0 * 16 + h) * SEQ + t0) * DH;
            size_t o1 = ((size_t)(b1 * 16 + h) * SEQ + t1) * DH;
#pragma unroll
            for (int nf = 0; nf < 8; nf++) {
                int d = wn * 64 + nf * 8 + 2 * t;
                *(uint32_t*)(vh + o0 + d) = fp16_pack2(acc[mf][nf][0], acc[mf][nf][1]);
                *(uint32_t*)(vh + o1 + d) = fp16_pack2(acc[mf][nf][2], acc[mf][nf][3]);
            }
        }
    } else {
        // Q/K: stage fp32 tile (64 rows/batch), apply RoPE, write fp16
        float* stage = (float*)gsm;
        const float qscale = 0.08838834764831845f;
#pragma unroll
        for (int half = 0; half < 2; half++) {
            __syncthreads();
            if ((wm >> 1) == half) {
                int baserow = wm * 32 - half * 64;   // 0 or 32
#pragma unroll
                for (int mf = 0; mf < 2; mf++) {
                    int lr0 = baserow + mf * 16 + g;
#pragma unroll
                    for (int nf = 0; nf < 8; nf++) {
                        int col = wn * 64 + nf * 8 + 2 * t;
                        stage[lr0 * RLD + col]           = acc[mf][nf][0];
                        stage[lr0 * RLD + col + 1]       = acc[mf][nf][1];
                        stage[(lr0 + 8) * RLD + col]     = acc[mf][nf][2];
                        stage[(lr0 + 8) * RLD + col + 1] = acc[mf][nf][3];
                    }
                }
            }
            __syncthreads();
#pragma unroll
            for (int it = 0; it < 32; it++) {
                int idx = tid + it * 256;
                int lr = idx >> 7, d = idx & 127;
                int m = m0 + half * 64 + lr;
                int trow = m & 2047, b = m >> 11;
                float val = stage[lr * RLD + d];
                float par = stage[lr * RLD + (d ^ 64)];
                int ci = d & 63;
                float c  = gcos[trow * 64 + ci];
                float sn = gsin[trow * 64 + ci];
                float rot = (d < 64) ? -par : par;
                float outv = val * c + rot * sn;
                size_t o = ((size_t)(b * 16 + h) * SEQ + trow) * DH + d;
                if (part == 0) qh[o] = __float2half_rn(outv * qscale);
                else           kh[o] = __float2half_rn(outv);
            }
        }
    }
}

// ===== plain fp16 HMMA GEMM (output projection): C = A * W^T, fp32 out =======
__global__ __launch_bounds__(256, 2)
void gemm_fp16_kernel(const __half* __restrict__ A,
                      const __half* __restrict__ W,
                      float* __restrict__ C, int M, int N, int K) {
    extern __shared__ char gsm[];
    const uint32_t sb = smem_u32(gsm);

    const int tid  = threadIdx.x;
    const int warp = tid >> 5, lane = tid & 31;
    const int g = lane >> 2, t = lane & 3;
    const int wm = warp & 3, wn = warp >> 2;
    const int m0 = blockIdx.y * 128;
    const int n0 = blockIdx.x * 128;
    const int NT = K / 32;

    float acc[2][8][4];
#pragma unroll
    for (int mf = 0; mf < 2; mf++)
#pragma unroll
        for (int nf = 0; nf < 8; nf++)
#pragma unroll
            for (int r = 0; r < 4; r++) acc[mf][nf][r] = 0.0f;

    auto prefetch = [&](int s, int kt) {
#pragma unroll
        for (int it = 0; it < 4; it++) {
            int i = tid + it * 256;
            int arr = i >> 9;
            int row = (i >> 2) & 127;
            int ch  = i & 3;
            const __half* src =
                (arr == 0) ? A + (size_t)(m0 + row) * K :
                             W + (size_t)(n0 + row) * K;
            src += kt * 32 + ch * 8;
            uint32_t dst = sb + (uint32_t)(s * GSTG + arr * GARR + row * 80 + ch * 16);
            CP_ASYNC16(dst, src);
        }
    };

    prefetch(0, 0);
    CP_COMMIT();

    for (int kt = 0; kt < NT; kt++) {
        if (kt + 1 < NT) {
            prefetch((kt + 1) & 1, kt + 1);
            CP_COMMIT();
            CP_WAIT1();
        } else {
            CP_WAIT0();
        }
        __syncthreads();

        const __half* As = (const __half*)(gsm + (size_t)(kt & 1) * GSTG);
        const __half* Ws = As + GARR / 2;

#pragma unroll
        for (int kk = 0; kk < 32; kk += 16) {
            uint32_t a[2][4];
#pragma unroll
            for (int mf = 0; mf < 2; mf++) {
                int r = wm * 32 + mf * 16 + g;
                const __half* p = &As[r * SLD + kk + 2 * t];
                a[mf][0] = *(const uint32_t*)p;
                a[mf][1] = *(const uint32_t*)(p + 8 * SLD);
                a[mf][2] = *(const uint32_t*)(p + 8);
                a[mf][3] = *(const uint32_t*)(p + 8 * SLD + 8);
            }
#pragma unroll
            for (int nf = 0; nf < 8; nf++) {
                const __half* p = &Ws[(wn * 64 + nf * 8 + g) * SLD + kk + 2 * t];
                uint32_t w0 = *(const uint32_t*)p;
                uint32_t w1 = *(const uint32_t*)(p + 8);
#pragma unroll
                for (int mf = 0; mf < 2; mf++)
                    MMA16816(acc[mf][nf], a[mf][0], a[mf][1], a[mf][2], a[mf][3], w0, w1);
            }
        }
        __syncthreads();
    }

#pragma unroll
    for (int mf = 0; mf < 2; mf++) {
        int r0 = m0 + wm * 32 + mf * 16 + g;
#pragma unroll
        for (int nf = 0; nf < 8; nf++) {
            int col = n0 + wn * 64 + nf * 8 + 2 * t;
            float* p0 = C + (size_t)r0 * N + col;
            float* p1 = C + (size_t)(r0 + 8) * N + col;
            *(float2*)p0 = make_float2(acc[mf][nf][0], acc[mf][nf][1]);
            *(float2*)p1 = make_float2(acc[mf][nf][2], acc[mf][nf][3]);
        }
    }
}

// ============ flash attention on HMMA (all plain fp16) =======================
#define FBQ 128
#define FBK 64
#define FLD 136
#define ARRB 17408u
#define STG_B (2 * 17408)
#define FA2_SMEM (2 * STG_B)

__global__ __launch_bounds__(256, 1)
void flash_mma_kernel(const __half* __restrict__ Qg,
                      const __half* __restrict__ KH,
                      const __half* __restrict__ VH,
                      __half* __restrict__ Yh) {
    extern __shared__ char smc[];
    const uint32_t sbase = smem_u32(smc);

    const int tid  = threadIdx.x;
    const int w    = tid >> 5, lane = tid & 31;
    const int g    = lane >> 2, t = lane & 3;
    const int qi   = gridDim.x - 1 - blockIdx.x;
    const int bh   = blockIdx.y;
    const int qbase = qi * FBQ;
    const int rowmax_w = qbase + w * 16 + 15;

    const size_t bhoff = (size_t)bh * SEQ * DH;

    uint32_t qf[8][4];
    {
        const __half* q0 = Qg + bhoff + (size_t)(qbase + w * 16 + g) * DH;
        const __half* q1 = q0 + 8 * DH;
#pragma unroll
        for (int kf = 0; kf < 8; kf++) {
            qf[kf][0] = *(const uint32_t*)(q0 + 16 * kf + 2 * t);
            qf[kf][1] = *(const uint32_t*)(q1 + 16 * kf + 2 * t);
            qf[kf][2] = *(const uint32_t*)(q0 + 16 * kf + 2 * t + 8);
            qf[kf][3] = *(const uint32_t*)(q1 + 16 * kf + 2 * t + 8);
        }
    }

    const uint32_t lmK = (uint32_t)(((lane & 7) * FLD + (lane >> 3) * 8) * 2);
    const uint32_t lmV = (uint32_t)((((lane & 7) + ((lane >> 3) & 1) * 8) * FLD
                                     + (lane >> 4) * 8) * 2);

    float m0r = -1e30f, m1r = -1e30f, l0r = 0.0f, l1r = 0.0f;
    float o[16][4];
#pragma unroll
    for (int nf = 0; nf < 16; nf++)
#pragma unroll
        for (int r = 0; r < 4; r++) o[nf][r] = 0.0f;

    const int nkt = 2 * qi + 2;

    auto prefetch = [&](int s, int kt) {
        const int kb = kt * FBK;
        const __half* srcs[2] = { KH + bhoff + (size_t)kb * DH,
                                  VH + bhoff + (size_t)kb * DH };
        uint32_t dst0 = sbase + (uint32_t)s * STG_B;
#pragma unroll
        for (int it = 0; it < 8; it++) {
            int i = tid + it * 256;
            int arr = i >> 10, key = (i >> 4) & 63, ch = i & 15;
            const __half* src = srcs[arr] + key * DH + ch * 8;
            uint32_t dst = dst0 + (uint32_t)(arr * ARRB + key * 272 + ch * 16);
            CP_ASYNC16(dst, src);
        }
    };

    prefetch(0, 0);
    CP_COMMIT();

    for (int kt = 0; kt < nkt; kt++) {
        if (kt + 1 < nkt) {
            prefetch((kt + 1) & 1, kt + 1);
            CP_COMMIT();
            CP_WAIT1();
        } else {
            CP_WAIT0();
        }
        __syncthreads();

        const int kbase = kt * FBK;
        const bool active = (kbase <= rowmax_w);
        if (active) {
            const uint32_t stg = sbase + (uint32_t)(kt & 1) * STG_B;

            float s[8][4];
#pragma unroll
            for (int nf = 0; nf < 8; nf++)
#pragma unroll
                for (int r = 0; r < 4; r++) s[nf][r] = 0.0f;

#pragma unroll
            for (int kf2 = 0; kf2 < 4; kf2++) {
#pragma unroll
                for (int nf = 0; nf < 8; nf++) {
                    uint32_t off = (uint32_t)((nf * 8 * FLD + kf2 * 32) * 2);
                    uint32_t k0, k1, k2, k3;
                    LDSM_X4(k0, k1, k2, k3, stg + lmK + off);
                    MMA16816(s[nf], qf[2*kf2][0], qf[2*kf2][1], qf[2*kf2][2], qf[2*kf2][3], k0, k1);
                    MMA16816(s[nf], qf[2*kf2+1][0], qf[2*kf2+1][1], qf[2*kf2+1][2], qf[2*kf2+1][3], k2, k3);
                }
            }

            const int row0 = qbase + w * 16 + g;
            const int row1 = row0 + 8;
            if (kbase + FBK - 1 > qbase + w * 16) {
#pragma unroll
                for (int nf = 0; nf < 8; nf++) {
                    int c0 = kbase + 8 * nf + 2 * t;
                    if (c0 > row0)     s[nf][0] = -1e30f;
                    if (c0 + 1 > row0) s[nf][1] = -1e30f;
                    if (c0 > row1)     s[nf][2] = -1e30f;
                    if (c0 + 1 > row1) s[nf][3] = -1e30f;
                }
            }

            float mx0 = -1e30f, mx1 = -1e30f;
#pragma unroll
            for (int nf = 0; nf < 8; nf++) {
                mx0 = fmaxf(mx0, fmaxf(s[nf][0], s[nf][1]));
                mx1 = fmaxf(mx1, fmaxf(s[nf][2], s[nf][3]));
            }
            mx0 = fmaxf(mx0, __shfl_xor_sync(0xffffffffu, mx0, 1));
            mx0 = fmaxf(mx0, __shfl_xor_sync(0xffffffffu, mx0, 2));
            mx1 = fmaxf(mx1, __shfl_xor_sync(0xffffffffu, mx1, 1));
            mx1 = fmaxf(mx1, __shfl_xor_sync(0xffffffffu, mx1, 2));
            float mn0 = fmaxf(m0r, mx0), mn1 = fmaxf(m1r, mx1);
            float a0 = __expf(m0r - mn0), a1 = __expf(m1r - mn1);
            m0r = mn0; m1r = mn1;
            float rs0 = 0.0f, rs1 = 0.0f;
#pragma unroll
            for (int nf = 0; nf < 8; nf++) {
                s[nf][0] = __expf(s[nf][0] - mn0);
                s[nf][1] = __expf(s[nf][1] - mn0);
                s[nf][2] = __expf(s[nf][2] - mn1);
                s[nf][3] = __expf(s[nf][3] - mn1);
                rs0 += s[nf][0] + s[nf][1];
                rs1 += s[nf][2] + s[nf][3];
            }
            rs0 += __shfl_xor_sync(0xffffffffu, rs0, 1);
            rs0 += __shfl_xor_sync(0xffffffffu, rs0, 2);
            rs1 += __shfl_xor_sync(0xffffffffu, rs1, 1);
            rs1 += __shfl_xor_sync(0xffffffffu, rs1, 2);
            l0r = l0r * a0 + rs0;
            l1r = l1r * a1 + rs1;
#pragma unroll
            for (int nf = 0; nf < 16; nf++) {
                o[nf][0] *= a0; o[nf][1] *= a0;
                o[nf][2] *= a1; o[nf][3] *= a1;
            }

#pragma unroll
            for (int kf = 0; kf < 4; kf++) {
                uint32_t ph[4];
                ph[0] = fp16_pack2(s[2*kf][0],   s[2*kf][1]);
                ph[1] = fp16_pack2(s[2*kf][2],   s[2*kf][3]);
                ph[2] = fp16_pack2(s[2*kf+1][0], s[2*kf+1][1]);
                ph[3] = fp16_pack2(s[2*kf+1][2], s[2*kf+1][3]);
                uint32_t voff = (uint32_t)((kf * 16 * FLD) * 2);
#pragma unroll
                for (int nf2 = 0; nf2 < 8; nf2++) {
                    uint32_t off = voff + (uint32_t)(nf2 * 32);
                    uint32_t v0, v1, v2, v3;
                    LDSM_X4T(v0, v1, v2, v3, stg + ARRB + lmV + off);
                    MMA16816(o[2*nf2],   ph[0], ph[1], ph[2], ph[3], v0, v1);
                    MMA16816(o[2*nf2+1], ph[0], ph[1], ph[2], ph[3], v2, v3);
                }
            }
        }
        __syncthreads();
    }

    const int b = bh >> 4, h = bh & 15;
    const int row0 = qbase + w * 16 + g;
    const float inv0 = 1.0f / l0r, inv1 = 1.0f / l1r;
    size_t y0off = ((size_t)(b * SEQ + row0)) * NEMBD + h * DH;
    size_t y1off = ((size_t)(b * SEQ + row0 + 8)) * NEMBD + h * DH;
#pragma unroll
    for (int nf = 0; nf < 16; nf++) {
        int col = 8 * nf + 2 * t;
        *(uint32_t*)(Yh + y0off + col) = fp16_pack2(o[nf][0] * inv0, o[nf][1] * inv0);
        *(uint32_t*)(Yh + y1off + col) = fp16_pack2(o[nf][2] * inv1, o[nf][3] * inv1);
    }
}

// ================= launch =====================================================
extern "C" void kernel_launch(void* const* d_in, const int* in_sizes, int n_in,
                              void* d_out, int out_size) {
    const float* x      = (const float*)d_in[0];
    const float* w_qkv  = (const float*)d_in[1];
    const float* w_proj = (const float*)d_in[2];
    float* out = (float*)d_out;

    float *gc, *gs;
    __half *qh, *kh, *vh, *xh, *wq, *wp, *yh;
    cudaGetSymbolAddress((void**)&qh, g_qh);
    cudaGetSymbolAddress((void**)&kh, g_kh);
    cudaGetSymbolAddress((void**)&vh, g_vh);
    cudaGetSymbolAddress((void**)&xh, g_xh);
    cudaGetSymbolAddress((void**)&wq, g_wq);
    cudaGetSymbolAddress((void**)&wp, g_wp);
    cudaGetSymbolAddress((void**)&yh, g_yh);
    cudaGetSymbolAddress((void**)&gc, g_cos);
    cudaGetSymbolAddress((void**)&gs, g_sin);

    // 1) RoPE tables + operand conversions
    rope_table_kernel<<<(SEQ * 64 + 255) / 256, 256>>>(gc, gs);
    {
        long long n4;
        n4 = (long long)MROWS * NEMBD / 4;
        cvt_kernel<<<(unsigned)((n4 + 255) / 256), 256>>>(x, xh, n4);
        n4 = (long long)QKV_N * NEMBD / 4;
        cvt_kernel<<<(unsigned)((n4 + 255) / 256), 256>>>(w_qkv, wq, n4);
        n4 = (long long)NEMBD * NEMBD / 4;
        cvt_kernel<<<(unsigned)((n4 + 255) / 256), 256>>>(w_proj, wp, n4);
    }

    // 2) QKV projection + fused RoPE -> qh(scaled)/kh/vh fp16
    cudaFuncSetAttribute(gemm_qkv_rope_kernel,
                         cudaFuncAttributeMaxDynamicSharedMemorySize, GEMM_SMEM);
    gemm_qkv_rope_kernel<<<dim3(QKV_N / 128, MROWS / 128), 256, GEMM_SMEM>>>(
        xh, wq, gc, gs, qh, kh, vh);

    // 3) flash attention (plain fp16 HMMA) -> y fp16
    cudaFuncSetAttribute(flash_mma_kernel,
                         cudaFuncAttributeMaxDynamicSharedMemorySize, FA2_SMEM);
    flash_mma_kernel<<<dim3(SEQ / FBQ, BHN), 256, FA2_SMEM>>>(
        qh, kh, vh, yh);

    // 4) output projection (plain fp16 HMMA, fp32 out)
    cudaFuncSetAttribute(gemm_fp16_kernel,
                         cudaFuncAttributeMaxDynamicSharedMemorySize, GEMM_SMEM);
    gemm_fp16_kernel<<<dim3(NEMBD / 128, MROWS / 128), 256, GEMM_SMEM>>>(
        yh, wp, out, MROWS, NEMBD, NEMBD);
}